// round 2
// baseline (speedup 1.0000x reference)
#include <cuda_runtime.h>

#define D     128
#define HID   256
#define TM    32
#define NTHR  256
#define MAXN  40000

// Scratch (device globals: no allocations allowed)
__device__ float g_agg[(size_t)MAXN * D];
__device__ float g_cnt[MAXN];
__device__ int   g_idx_is64;

// ---------------------------------------------------------------------------
// Detect edge_index dtype: int64 values < 2^31 have zero odd 32-bit words.
// ---------------------------------------------------------------------------
__global__ void detect_idx_kernel(const unsigned int* __restrict__ raw) {
    if (threadIdx.x == 0 && blockIdx.x == 0) {
        int is64 = 1;
        for (int i = 0; i < 32; ++i)
            if (raw[2 * i + 1] != 0u) { is64 = 0; break; }
        g_idx_is64 = is64;
    }
}

__device__ __forceinline__ int load_index(const void* idx, size_t pos, int n) {
    int v;
    if (g_idx_is64) v = (int)((const long long*)idx)[pos];
    else            v = ((const int*)idx)[pos];
    // clamp: never crash on a bad decode — surface as rel_err instead
    v = v < 0 ? 0 : (v >= n ? n - 1 : v);
    return v;
}

// ---------------------------------------------------------------------------
// GEMM1: hs[m][n] = silu(sum_k xs[m][k] * W1[k][n] + b1[n]);  n = tid (0..255)
// xs: [TM][KIN] smem, W1: [KIN][256] global (L2-resident), hs: [TM][256] smem
// ---------------------------------------------------------------------------
template <int KIN>
__device__ __forceinline__ void gemm1_silu(const float* __restrict__ xs,
                                           const float* __restrict__ W1,
                                           const float* __restrict__ b1,
                                           float* __restrict__ hs, int t) {
    float acc[TM];
#pragma unroll
    for (int m = 0; m < TM; ++m) acc[m] = 0.f;
    const int n = t;
#pragma unroll 2
    for (int k0 = 0; k0 < KIN; k0 += 4) {
        const float w0 = W1[(k0 + 0) * HID + n];
        const float w1 = W1[(k0 + 1) * HID + n];
        const float w2 = W1[(k0 + 2) * HID + n];
        const float w3 = W1[(k0 + 3) * HID + n];
#pragma unroll
        for (int m = 0; m < TM; ++m) {
            const float4 x = *(const float4*)&xs[m * KIN + k0];
            acc[m] = fmaf(x.x, w0, acc[m]);
            acc[m] = fmaf(x.y, w1, acc[m]);
            acc[m] = fmaf(x.z, w2, acc[m]);
            acc[m] = fmaf(x.w, w3, acc[m]);
        }
    }
    const float bb = b1[n];
#pragma unroll
    for (int m = 0; m < TM; ++m) {
        const float v = acc[m] + bb;
        hs[m * HID + n] = v / (1.f + __expf(-v));   // SiLU
    }
}

// ---------------------------------------------------------------------------
// GEMM2: ys[m][n] = sum_k hs[m][k] * W2[k][n] + b2[n]
// 256 threads cover 32x128 outputs: n = t&127, rows (t>>7)*16 .. +16
// ---------------------------------------------------------------------------
__device__ __forceinline__ void gemm2(const float* __restrict__ hs,
                                      const float* __restrict__ W2,
                                      const float* __restrict__ b2,
                                      float* __restrict__ ys, int t) {
    const int n  = t & (D - 1);
    const int m0 = (t >> 7) << 4;
    float acc[16];
#pragma unroll
    for (int m = 0; m < 16; ++m) acc[m] = 0.f;
#pragma unroll 2
    for (int k0 = 0; k0 < HID; k0 += 4) {
        const float w0 = W2[(k0 + 0) * D + n];
        const float w1 = W2[(k0 + 1) * D + n];
        const float w2 = W2[(k0 + 2) * D + n];
        const float w3 = W2[(k0 + 3) * D + n];
#pragma unroll
        for (int mm = 0; mm < 16; ++mm) {
            const float4 h = *(const float4*)&hs[(m0 + mm) * HID + k0];
            acc[mm] = fmaf(h.x, w0, acc[mm]);
            acc[mm] = fmaf(h.y, w1, acc[mm]);
            acc[mm] = fmaf(h.z, w2, acc[mm]);
            acc[mm] = fmaf(h.w, w3, acc[mm]);
        }
    }
    const float bb = b2[n];
#pragma unroll
    for (int mm = 0; mm < 16; ++mm) ys[(m0 + mm) * D + n] = acc[mm] + bb;
}

// ---------------------------------------------------------------------------
// LayerNorm + residual epilogue (node / sender kernels).
// warp w handles rows 4w..4w+3; lane covers cols lane, lane+32, lane+64, lane+96
// ---------------------------------------------------------------------------
__device__ __forceinline__ void ln_residual(const float* __restrict__ ys,
                                            const float* __restrict__ gamma,
                                            const float* __restrict__ beta,
                                            const float* __restrict__ resid,
                                            float* __restrict__ out,
                                            int row0, int t) {
    const int warp = t >> 5, lane = t & 31;
    for (int r = warp * 4; r < warp * 4 + 4; ++r) {
        float v[4], s = 0.f, ss = 0.f;
#pragma unroll
        for (int j = 0; j < 4; ++j) {
            v[j] = ys[r * D + lane + 32 * j];
            s += v[j]; ss += v[j] * v[j];
        }
#pragma unroll
        for (int o = 16; o > 0; o >>= 1) {
            s  += __shfl_xor_sync(0xFFFFFFFFu, s,  o);
            ss += __shfl_xor_sync(0xFFFFFFFFu, ss, o);
        }
        const float mu  = s * (1.f / D);
        const float inv = rsqrtf(ss * (1.f / D) - mu * mu + 1e-5f);
        const size_t off = (size_t)(row0 + r) * D;
#pragma unroll
        for (int j = 0; j < 4; ++j) {
            const int c = lane + 32 * j;
            const float p = (v[j] - mu) * inv * gamma[c] + beta[c];
            out[off + c] = resid[off + c] + p;
        }
    }
}

// ---------------------------------------------------------------------------
// Kernel A: edge MLP + LN, writes edge_out, scatters message into g_agg/g_cnt
// ---------------------------------------------------------------------------
__global__ __launch_bounds__(NTHR) void edge_kernel(
    const float* __restrict__ sender_x, const float* __restrict__ receiver_x,
    const float* __restrict__ edge_attr, const void* __restrict__ edge_index,
    const float* __restrict__ ew1, const float* __restrict__ eb1,
    const float* __restrict__ ew2, const float* __restrict__ eb2,
    const float* __restrict__ eg, const float* __restrict__ ebeta,
    float* __restrict__ edge_out, int E, int N) {
    extern __shared__ float sm[];
    float* xs = sm;                 // [32][384]
    float* hs = sm + TM * 384;      // [32][256]
    float* ys = sm;                 // [32][128] (aliases xs; xs dead by then)
    __shared__ int s_src[TM], s_dst[TM];

    const int t  = threadIdx.x;
    const int e0 = blockIdx.x * TM;
    if (t < TM)           s_src[t]      = load_index(edge_index, e0 + t, N);
    else if (t < 2 * TM)  s_dst[t - TM] = load_index(edge_index, (size_t)E + e0 + (t - TM), N);
    __syncthreads();

    // gather concat(sender_x[src], receiver_x[dst], edge_attr[e]) -> xs
    for (int i = t; i < TM * 96; i += NTHR) {
        const int m = i / 96, c4 = (i % 96) * 4;
        float4 v;
        if (c4 < 128)       v = *(const float4*)&sender_x[(size_t)s_src[m] * D + c4];
        else if (c4 < 256)  v = *(const float4*)&receiver_x[(size_t)s_dst[m] * D + (c4 - 128)];
        else                v = *(const float4*)&edge_attr[(size_t)(e0 + m) * D + (c4 - 256)];
        *(float4*)&xs[m * 384 + c4] = v;
    }
    __syncthreads();

    gemm1_silu<384>(xs, ew1, eb1, hs, t);
    __syncthreads();
    gemm2(hs, ew2, eb2, ys, t);
    __syncthreads();

    // LN + residual edge_out + scatter (mean numerator/denominator)
    const int warp = t >> 5, lane = t & 31;
    for (int r = warp * 4; r < warp * 4 + 4; ++r) {
        float v[4], s = 0.f, ss = 0.f;
#pragma unroll
        for (int j = 0; j < 4; ++j) {
            v[j] = ys[r * D + lane + 32 * j];
            s += v[j]; ss += v[j] * v[j];
        }
#pragma unroll
        for (int o = 16; o > 0; o >>= 1) {
            s  += __shfl_xor_sync(0xFFFFFFFFu, s,  o);
            ss += __shfl_xor_sync(0xFFFFFFFFu, ss, o);
        }
        const float mu  = s * (1.f / D);
        const float inv = rsqrtf(ss * (1.f / D) - mu * mu + 1e-5f);
        const int e = e0 + r, dn = s_dst[r];
        const size_t eoff = (size_t)e * D;
#pragma unroll
        for (int j = 0; j < 4; ++j) {
            const int c = lane + 32 * j;
            const float p = (v[j] - mu) * inv * eg[c] + ebeta[c];
            edge_out[eoff + c] = edge_attr[eoff + c] + p;
            atomicAdd(&g_agg[(size_t)dn * D + c], p);
        }
        if (lane == 0) atomicAdd(&g_cnt[dn], 1.f);
    }
}

// ---------------------------------------------------------------------------
// Kernel B: node MLP on concat(receiver_x, mean-aggregated messages)
// ---------------------------------------------------------------------------
__global__ __launch_bounds__(NTHR) void node_kernel(
    const float* __restrict__ receiver_x,
    const float* __restrict__ nw1, const float* __restrict__ nb1,
    const float* __restrict__ nw2, const float* __restrict__ nb2,
    const float* __restrict__ ng, const float* __restrict__ nbeta,
    float* __restrict__ receiver_out) {
    extern __shared__ float sm[];
    float* xs = sm;                 // [32][256]
    float* hs = sm + TM * 256;      // [32][256]
    float* ys = sm;
    __shared__ float s_inv[TM];
    const int t  = threadIdx.x;
    const int i0 = blockIdx.x * TM;
    if (t < TM) s_inv[t] = 1.f / fmaxf(g_cnt[i0 + t], 1.f);
    __syncthreads();

    for (int i = t; i < TM * 64; i += NTHR) {
        const int m = i / 64, c4 = (i % 64) * 4;
        float4 v;
        if (c4 < 128) {
            v = *(const float4*)&receiver_x[(size_t)(i0 + m) * D + c4];
        } else {
            v = *(const float4*)&g_agg[(size_t)(i0 + m) * D + (c4 - 128)];
            const float sc = s_inv[m];
            v.x *= sc; v.y *= sc; v.z *= sc; v.w *= sc;
        }
        *(float4*)&xs[m * 256 + c4] = v;
    }
    __syncthreads();

    gemm1_silu<256>(xs, nw1, nb1, hs, t);
    __syncthreads();
    gemm2(hs, nw2, nb2, ys, t);
    __syncthreads();
    ln_residual(ys, ng, nbeta, receiver_x, receiver_out, i0, t);
}

// ---------------------------------------------------------------------------
// Kernel C: sender MLP (D -> H -> D) + LN + residual
// ---------------------------------------------------------------------------
__global__ __launch_bounds__(NTHR) void sender_kernel(
    const float* __restrict__ sender_x,
    const float* __restrict__ sw1, const float* __restrict__ sb1,
    const float* __restrict__ sw2, const float* __restrict__ sb2,
    const float* __restrict__ sg, const float* __restrict__ sbeta,
    float* __restrict__ sender_out) {
    extern __shared__ float sm[];
    float* xs = sm;                 // [32][128]
    float* hs = sm + TM * 128;      // [32][256]
    float* ys = sm;
    const int t  = threadIdx.x;
    const int i0 = blockIdx.x * TM;

    for (int i = t; i < TM * 32; i += NTHR) {
        const int m = i / 32, c4 = (i % 32) * 4;
        *(float4*)&xs[m * 128 + c4] =
            *(const float4*)&sender_x[(size_t)(i0 + m) * D + c4];
    }
    __syncthreads();

    gemm1_silu<128>(xs, sw1, sb1, hs, t);
    __syncthreads();
    gemm2(hs, sw2, sb2, ys, t);
    __syncthreads();
    ln_residual(ys, sg, sbeta, sender_x, sender_out, i0, t);
}

// ---------------------------------------------------------------------------
__global__ void zero_scratch(int nAgg, int nCnt) {
    const int i = blockIdx.x * blockDim.x + threadIdx.x;
    if (i < nAgg) g_agg[i] = 0.f;
    if (i < nCnt) g_cnt[i] = 0.f;
}

extern "C" void kernel_launch(void* const* d_in, const int* in_sizes, int n_in,
                              void* d_out, int out_size) {
    const float* sender_x   = (const float*)d_in[0];
    const float* receiver_x = (const float*)d_in[1];
    const float* edge_attr  = (const float*)d_in[2];
    const void*  edge_index = d_in[3];
    const float* ew1 = (const float*)d_in[4];
    const float* eb1 = (const float*)d_in[5];
    const float* ew2 = (const float*)d_in[6];
    const float* eb2 = (const float*)d_in[7];
    const float* eg  = (const float*)d_in[8];
    const float* ebt = (const float*)d_in[9];
    const float* nw1 = (const float*)d_in[10];
    const float* nb1 = (const float*)d_in[11];
    const float* nw2 = (const float*)d_in[12];
    const float* nb2 = (const float*)d_in[13];
    const float* ng  = (const float*)d_in[14];
    const float* nbt = (const float*)d_in[15];
    const float* sw1 = (const float*)d_in[16];
    const float* sb1 = (const float*)d_in[17];
    const float* sw2 = (const float*)d_in[18];
    const float* sb2 = (const float*)d_in[19];
    const float* sg  = (const float*)d_in[20];
    const float* sbt = (const float*)d_in[21];

    const int N = in_sizes[0] / D;     // 40000
    const int E = in_sizes[2] / D;     // 640000

    float* out          = (float*)d_out;
    float* sender_out   = out;
    float* receiver_out = out + (size_t)N * D;
    float* edge_out     = out + (size_t)2 * N * D;

    const int smemA = (TM * 384 + TM * 256) * sizeof(float);  // 81920
    const int smemB = (TM * 256 + TM * 256) * sizeof(float);  // 65536
    const int smemC = (TM * 128 + TM * 256) * sizeof(float);  // 49152
    cudaFuncSetAttribute(edge_kernel,   cudaFuncAttributeMaxDynamicSharedMemorySize, smemA);
    cudaFuncSetAttribute(node_kernel,   cudaFuncAttributeMaxDynamicSharedMemorySize, smemB);
    cudaFuncSetAttribute(sender_kernel, cudaFuncAttributeMaxDynamicSharedMemorySize, smemC);

    detect_idx_kernel<<<1, 32>>>((const unsigned int*)edge_index);

    const int nAgg = N * D;
    zero_scratch<<<(nAgg + NTHR - 1) / NTHR, NTHR>>>(nAgg, N);

    edge_kernel<<<E / TM, NTHR, smemA>>>(sender_x, receiver_x, edge_attr, edge_index,
                                         ew1, eb1, ew2, eb2, eg, ebt, edge_out, E, N);
    node_kernel<<<N / TM, NTHR, smemB>>>(receiver_x, nw1, nb1, nw2, nb2, ng, nbt,
                                         receiver_out);
    sender_kernel<<<N / TM, NTHR, smemC>>>(sender_x, sw1, sb1, sw2, sb2, sg, sbt,
                                           sender_out);
}

// round 3
// speedup vs baseline: 2.4283x; 2.4283x over previous
#include <cuda_runtime.h>
#include <cstdint>

#define D     128
#define HID   256
#define TM    64
#define NTHR  256
#define MAXN  40000

// smem layout (floats): [0..25088) A/hs/ys region, [25088..33280) B double buffer
#define YS_OFF   16640      // 64*260
#define SB_OFF   25088
#define SMEM_BYTES ((25088 + 8192) * 4)

// Scratch (device globals: no allocations allowed)
__device__ float g_agg[(size_t)MAXN * D];
__device__ float g_cnt[MAXN];
__device__ int   g_idx_is64;
__device__ float g_wp[294912];          // packed tf32 weights
#define OFF_EW1 0
#define OFF_EW2 98304
#define OFF_NW1 131072
#define OFF_NW2 196608
#define OFF_SW1 229376
#define OFF_SW2 262144

// ---------------------------------------------------------------------------
__device__ __forceinline__ uint32_t f2tf(float x) {
    uint32_t r; asm("cvt.rna.tf32.f32 %0, %1;" : "=r"(r) : "f"(x)); return r;
}
__device__ __forceinline__ float silu(float v) { return v / (1.f + __expf(-v)); }

__device__ __forceinline__ void mma8(float* c, const uint32_t* a,
                                     uint32_t b0, uint32_t b1) {
    asm volatile(
        "mma.sync.aligned.m16n8k8.row.col.f32.tf32.tf32.f32 "
        "{%0,%1,%2,%3},{%4,%5,%6,%7},{%8,%9},{%0,%1,%2,%3};"
        : "+f"(c[0]), "+f"(c[1]), "+f"(c[2]), "+f"(c[3])
        : "r"(a[0]), "r"(a[1]), "r"(a[2]), "r"(a[3]), "r"(b0), "r"(b1));
}

// ---------------------------------------------------------------------------
// Detect edge_index dtype: int64 values < 2^31 have zero odd 32-bit words.
// ---------------------------------------------------------------------------
__global__ void detect_idx_kernel(const unsigned int* __restrict__ raw) {
    if (threadIdx.x == 0 && blockIdx.x == 0) {
        int is64 = 1;
        for (int i = 0; i < 32; ++i)
            if (raw[2 * i + 1] != 0u) { is64 = 0; break; }
        g_idx_is64 = is64;
    }
}
__device__ __forceinline__ int load_index(const void* idx, size_t pos, int n) {
    int v;
    if (g_idx_is64) v = (int)((const long long*)idx)[pos];
    else            v = ((const int*)idx)[pos];
    return v < 0 ? 0 : (v >= n ? n - 1 : v);
}

// ---------------------------------------------------------------------------
// Pack W[K][Nn] (row-major) into fragment order, tf32-rounded:
// float4 i = ((s * Nn/16 + p) * 32 + lane): {B[s8+q][p16+g], B[s8+q+4][p16+g],
//                                            B[s8+q][p16+8+g], B[s8+q+4][p16+8+g]}
// ---------------------------------------------------------------------------
__global__ void pack_kernel(const float* __restrict__ W, int dstOff, int K, int Nn) {
    const int i = blockIdx.x * blockDim.x + threadIdx.x;
    const int total = (K / 8) * (Nn / 16) * 32;
    if (i >= total) return;
    const int lane = i & 31, rest = i >> 5;
    const int NP = Nn / 16;
    const int p = rest % NP, s = rest / NP;
    const int g = lane >> 2, q = lane & 3;
    const float* r0 = W + (size_t)(s * 8 + q) * Nn + p * 16 + g;
    const float* r1 = W + (size_t)(s * 8 + q + 4) * Nn + p * 16 + g;
    float4 v;
    v.x = __uint_as_float(f2tf(r0[0]));
    v.y = __uint_as_float(f2tf(r1[0]));
    v.z = __uint_as_float(f2tf(r0[8]));
    v.w = __uint_as_float(f2tf(r1[8]));
    ((float4*)(g_wp + dstOff))[i] = v;
}

// ---------------------------------------------------------------------------
// Warp-cooperative GEMM: 8 warps = 2(M) x 4(N); warp tile M32 x N(16*WNT/2*2).
// A in smem [64][astride]; packed B streamed global->smem double buffer.
// acc layout: acc[(mi*WNT + nt)*4 + i], mi in 0..1 (m16 subtiles), nt ntiles.
// ---------------------------------------------------------------------------
template <int KIN, int NOUT, int WNT>
__device__ __forceinline__ void warp_gemm(const float* __restrict__ As, int astride,
                                          const float* __restrict__ Wp,
                                          float* __restrict__ sB,
                                          float* __restrict__ acc,
                                          int wm, int wn, int lane, int tid) {
    constexpr int NP    = NOUT / 16;      // pairs per k8 slice
    constexpr int WNP   = WNT / 2;        // pairs per warp
    constexpr int SLICE = NP * 128;       // floats per k8 slice
    constexpr int STAGE = 2 * SLICE;      // K_TILE = 16
    constexpr int NST   = KIN / 16;
    constexpr int PF    = STAGE / (4 * NTHR);
    const int g = lane >> 2, q = lane & 3;

#pragma unroll
    for (int i = 0; i < 2 * WNT * 4; ++i) acc[i] = 0.f;

    {   // stage 0
        const float4* src = (const float4*)Wp;
        float4* dst = (float4*)sB;
#pragma unroll
        for (int i = 0; i < PF; ++i) dst[i * NTHR + tid] = src[i * NTHR + tid];
    }
    __syncthreads();

#pragma unroll 1
    for (int st = 0; st < NST; ++st) {
        float4 pf[PF];
        if (st + 1 < NST) {
            const float4* src = (const float4*)(Wp + (size_t)(st + 1) * STAGE);
#pragma unroll
            for (int i = 0; i < PF; ++i) pf[i] = src[i * NTHR + tid];
        }
        const float* bb = sB + (st & 1) * STAGE;
#pragma unroll
        for (int s2 = 0; s2 < 2; ++s2) {
            const int k0 = st * 16 + s2 * 8;
            uint32_t af[2][4];
#pragma unroll
            for (int mi = 0; mi < 2; ++mi) {
                const float* ap = As + (wm * 32 + mi * 16 + g) * astride + k0 + q;
                af[mi][0] = f2tf(ap[0]);
                af[mi][1] = f2tf(ap[8 * astride]);
                af[mi][2] = f2tf(ap[4]);
                af[mi][3] = f2tf(ap[8 * astride + 4]);
            }
#pragma unroll
            for (int p = 0; p < WNP; ++p) {
                const float4 bv =
                    *(const float4*)(bb + ((s2 * NP + wn * WNP + p) * 32 + lane) * 4);
                const uint32_t b0 = __float_as_uint(bv.x), b1 = __float_as_uint(bv.y);
                const uint32_t b2 = __float_as_uint(bv.z), b3 = __float_as_uint(bv.w);
#pragma unroll
                for (int mi = 0; mi < 2; ++mi) {
                    mma8(acc + (mi * WNT + 2 * p) * 4,     af[mi], b0, b1);
                    mma8(acc + (mi * WNT + 2 * p + 1) * 4, af[mi], b2, b3);
                }
            }
        }
        if (st + 1 < NST) {
            float4* dst = (float4*)(sB + ((st + 1) & 1) * STAGE);
#pragma unroll
            for (int i = 0; i < PF; ++i) dst[i * NTHR + tid] = pf[i];
        }
        __syncthreads();
    }
}

// GEMM1 epilogue: bias + SiLU -> hs[64][260]
__device__ __forceinline__ void epi1(const float* acc, float* hs, const float* b1s,
                                     int wm, int wn, int lane) {
    const int g = lane >> 2, q = lane & 3;
#pragma unroll
    for (int mi = 0; mi < 2; ++mi)
#pragma unroll
        for (int nt = 0; nt < 8; ++nt) {
            const float* a  = acc + (mi * 8 + nt) * 4;
            const int r0  = wm * 32 + mi * 16 + g;
            const int col = wn * 64 + nt * 8 + 2 * q;
            hs[r0 * 260 + col]           = silu(a[0] + b1s[col]);
            hs[r0 * 260 + col + 1]       = silu(a[1] + b1s[col + 1]);
            hs[(r0 + 8) * 260 + col]     = silu(a[2] + b1s[col]);
            hs[(r0 + 8) * 260 + col + 1] = silu(a[3] + b1s[col + 1]);
        }
}

// GEMM2 epilogue: bias -> ys[64][132]
__device__ __forceinline__ void epi2(const float* acc, float* ys, const float* b2s,
                                     int wm, int wn, int lane) {
    const int g = lane >> 2, q = lane & 3;
#pragma unroll
    for (int mi = 0; mi < 2; ++mi)
#pragma unroll
        for (int nt = 0; nt < 4; ++nt) {
            const float* a  = acc + (mi * 4 + nt) * 4;
            const int r0  = wm * 32 + mi * 16 + g;
            const int col = wn * 32 + nt * 8 + 2 * q;
            ys[r0 * 132 + col]           = a[0] + b2s[col];
            ys[r0 * 132 + col + 1]       = a[1] + b2s[col + 1];
            ys[(r0 + 8) * 132 + col]     = a[2] + b2s[col];
            ys[(r0 + 8) * 132 + col + 1] = a[3] + b2s[col + 1];
        }
}

// ---------------------------------------------------------------------------
// Kernel A: edge MLP (3D->H->D) + LN + residual + scatter
// ---------------------------------------------------------------------------
__global__ __launch_bounds__(NTHR) void edge_kernel(
    const float* __restrict__ sender_x, const float* __restrict__ receiver_x,
    const float* __restrict__ edge_attr, const void* __restrict__ edge_index,
    const float* __restrict__ eb1, const float* __restrict__ eb2,
    const float* __restrict__ eg, const float* __restrict__ ebeta,
    float* __restrict__ edge_out, int E, int N) {
    extern __shared__ float sm[];
    float* A  = sm;              // [64][388]
    float* hs = sm;              // [64][260] (aliases A after GEMM1)
    float* ys = sm + YS_OFF;     // [64][132]
    float* sB = sm + SB_OFF;
    __shared__ int s_src[TM], s_dst[TM];
    __shared__ float s_b1[HID], s_b2[D], s_g[D], s_bt[D];

    const int tid = threadIdx.x;
    const int warp = tid >> 5, lane = tid & 31;
    const int wm = warp >> 2, wn = warp & 3;
    const int e0 = blockIdx.x * TM;

    if (tid < TM)          s_src[tid]      = load_index(edge_index, e0 + tid, N);
    else if (tid < 2 * TM) s_dst[tid - TM] = load_index(edge_index, (size_t)E + e0 + tid - TM, N);
    if (tid < HID) s_b1[tid] = eb1[tid];
    if (tid < D) { s_b2[tid] = eb2[tid]; s_g[tid] = eg[tid]; s_bt[tid] = ebeta[tid]; }
    __syncthreads();

    for (int i = tid; i < TM * 96; i += NTHR) {
        const int m = i / 96, c4 = (i % 96) * 4;
        float4 v;
        if (c4 < 128)      v = *(const float4*)&sender_x[(size_t)s_src[m] * D + c4];
        else if (c4 < 256) v = *(const float4*)&receiver_x[(size_t)s_dst[m] * D + (c4 - 128)];
        else               v = *(const float4*)&edge_attr[(size_t)(e0 + m) * D + (c4 - 256)];
        *(float4*)&A[m * 388 + c4] = v;
    }
    // warp_gemm's first __syncthreads orders the gather

    float acc1[64];
    warp_gemm<384, 256, 8>(A, 388, g_wp + OFF_EW1, sB, acc1, wm, wn, lane, tid);
    epi1(acc1, hs, s_b1, wm, wn, lane);
    __syncthreads();

    float acc2[32];
    warp_gemm<256, 128, 4>(hs, 260, g_wp + OFF_EW2, sB, acc2, wm, wn, lane, tid);
    epi2(acc2, ys, s_b2, wm, wn, lane);
    __syncthreads();

    // LN + residual + scatter, 8 rows per warp
    for (int r = warp * 8; r < warp * 8 + 8; ++r) {
        float v[4], s = 0.f, ss = 0.f;
#pragma unroll
        for (int j = 0; j < 4; ++j) {
            v[j] = ys[r * 132 + lane + 32 * j];
            s += v[j]; ss += v[j] * v[j];
        }
#pragma unroll
        for (int o = 16; o > 0; o >>= 1) {
            s  += __shfl_xor_sync(0xFFFFFFFFu, s,  o);
            ss += __shfl_xor_sync(0xFFFFFFFFu, ss, o);
        }
        const float mu  = s * (1.f / D);
        const float inv = rsqrtf(ss * (1.f / D) - mu * mu + 1e-5f);
        const int dn = s_dst[r];
        const size_t eoff = (size_t)(e0 + r) * D;
#pragma unroll
        for (int j = 0; j < 4; ++j) {
            const int c = lane + 32 * j;
            const float p = (v[j] - mu) * inv * s_g[c] + s_bt[c];
            edge_out[eoff + c] = edge_attr[eoff + c] + p;
            atomicAdd(&g_agg[(size_t)dn * D + c], p);
        }
        if (lane == 0) atomicAdd(&g_cnt[dn], 1.f);
    }
}

// ---------------------------------------------------------------------------
// Kernel B: node MLP (2D->H->D) + LN + residual
// ---------------------------------------------------------------------------
__global__ __launch_bounds__(NTHR) void node_kernel(
    const float* __restrict__ receiver_x,
    const float* __restrict__ nb1, const float* __restrict__ nb2,
    const float* __restrict__ ng, const float* __restrict__ nbeta,
    float* __restrict__ receiver_out) {
    extern __shared__ float sm[];
    float* A  = sm;              // [64][260]
    float* hs = sm;
    float* ys = sm + YS_OFF;
    float* sB = sm + SB_OFF;
    __shared__ float s_inv[TM];
    __shared__ float s_b1[HID], s_b2[D], s_g[D], s_bt[D];

    const int tid = threadIdx.x;
    const int warp = tid >> 5, lane = tid & 31;
    const int wm = warp >> 2, wn = warp & 3;
    const int i0 = blockIdx.x * TM;

    if (tid < TM) s_inv[tid] = 1.f / fmaxf(g_cnt[i0 + tid], 1.f);
    if (tid < HID) s_b1[tid] = nb1[tid];
    if (tid < D) { s_b2[tid] = nb2[tid]; s_g[tid] = ng[tid]; s_bt[tid] = nbeta[tid]; }
    __syncthreads();

    for (int i = tid; i < TM * 64; i += NTHR) {
        const int m = i / 64, c4 = (i % 64) * 4;
        float4 v;
        if (c4 < 128) {
            v = *(const float4*)&receiver_x[(size_t)(i0 + m) * D + c4];
        } else {
            v = *(const float4*)&g_agg[(size_t)(i0 + m) * D + (c4 - 128)];
            const float sc = s_inv[m];
            v.x *= sc; v.y *= sc; v.z *= sc; v.w *= sc;
        }
        *(float4*)&A[m * 260 + c4] = v;
    }

    float acc1[64];
    warp_gemm<256, 256, 8>(A, 260, g_wp + OFF_NW1, sB, acc1, wm, wn, lane, tid);
    epi1(acc1, hs, s_b1, wm, wn, lane);
    __syncthreads();

    float acc2[32];
    warp_gemm<256, 128, 4>(hs, 260, g_wp + OFF_NW2, sB, acc2, wm, wn, lane, tid);
    epi2(acc2, ys, s_b2, wm, wn, lane);
    __syncthreads();

    for (int r = warp * 8; r < warp * 8 + 8; ++r) {
        float v[4], s = 0.f, ss = 0.f;
#pragma unroll
        for (int j = 0; j < 4; ++j) {
            v[j] = ys[r * 132 + lane + 32 * j];
            s += v[j]; ss += v[j] * v[j];
        }
#pragma unroll
        for (int o = 16; o > 0; o >>= 1) {
            s  += __shfl_xor_sync(0xFFFFFFFFu, s,  o);
            ss += __shfl_xor_sync(0xFFFFFFFFu, ss, o);
        }
        const float mu  = s * (1.f / D);
        const float inv = rsqrtf(ss * (1.f / D) - mu * mu + 1e-5f);
        const size_t off = (size_t)(i0 + r) * D;
#pragma unroll
        for (int j = 0; j < 4; ++j) {
            const int c = lane + 32 * j;
            const float p = (v[j] - mu) * inv * s_g[c] + s_bt[c];
            receiver_out[off + c] = receiver_x[off + c] + p;
        }
    }
}

// ---------------------------------------------------------------------------
// Kernel C: sender MLP (D->H->D) + LN + residual
// ---------------------------------------------------------------------------
__global__ __launch_bounds__(NTHR) void sender_kernel(
    const float* __restrict__ sender_x,
    const float* __restrict__ sb1, const float* __restrict__ sb2,
    const float* __restrict__ sg, const float* __restrict__ sbeta,
    float* __restrict__ sender_out) {
    extern __shared__ float sm[];
    float* A  = sm;              // [64][132]
    float* hs = sm;
    float* ys = sm + YS_OFF;
    float* sB = sm + SB_OFF;
    __shared__ float s_b1[HID], s_b2[D], s_g[D], s_bt[D];

    const int tid = threadIdx.x;
    const int warp = tid >> 5, lane = tid & 31;
    const int wm = warp >> 2, wn = warp & 3;
    const int i0 = blockIdx.x * TM;

    if (tid < HID) s_b1[tid] = sb1[tid];
    if (tid < D) { s_b2[tid] = sb2[tid]; s_g[tid] = sg[tid]; s_bt[tid] = sbeta[tid]; }

    for (int i = tid; i < TM * 32; i += NTHR) {
        const int m = i / 32, c4 = (i % 32) * 4;
        *(float4*)&A[m * 132 + c4] =
            *(const float4*)&sender_x[(size_t)(i0 + m) * D + c4];
    }

    float acc1[64];
    warp_gemm<128, 256, 8>(A, 132, g_wp + OFF_SW1, sB, acc1, wm, wn, lane, tid);
    epi1(acc1, hs, s_b1, wm, wn, lane);
    __syncthreads();

    float acc2[32];
    warp_gemm<256, 128, 4>(hs, 260, g_wp + OFF_SW2, sB, acc2, wm, wn, lane, tid);
    epi2(acc2, ys, s_b2, wm, wn, lane);
    __syncthreads();

    for (int r = warp * 8; r < warp * 8 + 8; ++r) {
        float v[4], s = 0.f, ss = 0.f;
#pragma unroll
        for (int j = 0; j < 4; ++j) {
            v[j] = ys[r * 132 + lane + 32 * j];
            s += v[j]; ss += v[j] * v[j];
        }
#pragma unroll
        for (int o = 16; o > 0; o >>= 1) {
            s  += __shfl_xor_sync(0xFFFFFFFFu, s,  o);
            ss += __shfl_xor_sync(0xFFFFFFFFu, ss, o);
        }
        const float mu  = s * (1.f / D);
        const float inv = rsqrtf(ss * (1.f / D) - mu * mu + 1e-5f);
        const size_t off = (size_t)(i0 + r) * D;
#pragma unroll
        for (int j = 0; j < 4; ++j) {
            const int c = lane + 32 * j;
            const float p = (v[j] - mu) * inv * s_g[c] + s_bt[c];
            sender_out[off + c] = sender_x[off + c] + p;
        }
    }
}

// ---------------------------------------------------------------------------
__global__ void zero_scratch(int nAgg, int nCnt) {
    const int i = blockIdx.x * blockDim.x + threadIdx.x;
    if (i < nAgg) g_agg[i] = 0.f;
    if (i < nCnt) g_cnt[i] = 0.f;
}

extern "C" void kernel_launch(void* const* d_in, const int* in_sizes, int n_in,
                              void* d_out, int out_size) {
    const float* sender_x   = (const float*)d_in[0];
    const float* receiver_x = (const float*)d_in[1];
    const float* edge_attr  = (const float*)d_in[2];
    const void*  edge_index = d_in[3];
    const float* ew1 = (const float*)d_in[4];
    const float* eb1 = (const float*)d_in[5];
    const float* ew2 = (const float*)d_in[6];
    const float* eb2 = (const float*)d_in[7];
    const float* eg  = (const float*)d_in[8];
    const float* ebt = (const float*)d_in[9];
    const float* nw1 = (const float*)d_in[10];
    const float* nb1 = (const float*)d_in[11];
    const float* nw2 = (const float*)d_in[12];
    const float* nb2 = (const float*)d_in[13];
    const float* ng  = (const float*)d_in[14];
    const float* nbt = (const float*)d_in[15];
    const float* sw1 = (const float*)d_in[16];
    const float* sb1 = (const float*)d_in[17];
    const float* sw2 = (const float*)d_in[18];
    const float* sb2 = (const float*)d_in[19];
    const float* sg  = (const float*)d_in[20];
    const float* sbt = (const float*)d_in[21];

    const int N = in_sizes[0] / D;     // 40000
    const int E = in_sizes[2] / D;     // 640000

    float* out          = (float*)d_out;
    float* sender_out   = out;
    float* receiver_out = out + (size_t)N * D;
    float* edge_out     = out + (size_t)2 * N * D;

    cudaFuncSetAttribute(edge_kernel,   cudaFuncAttributeMaxDynamicSharedMemorySize, SMEM_BYTES);
    cudaFuncSetAttribute(node_kernel,   cudaFuncAttributeMaxDynamicSharedMemorySize, SMEM_BYTES);
    cudaFuncSetAttribute(sender_kernel, cudaFuncAttributeMaxDynamicSharedMemorySize, SMEM_BYTES);

    detect_idx_kernel<<<1, 32>>>((const unsigned int*)edge_index);

    // pack weights into tf32 fragment order
    auto pk = [](const float* w, int off, int K, int Nn) {
        const int tot = (K / 8) * (Nn / 16) * 32;
        pack_kernel<<<(tot + 255) / 256, 256>>>(w, off, K, Nn);
    };
    pk(ew1, OFF_EW1, 384, 256);
    pk(ew2, OFF_EW2, 256, 128);
    pk(nw1, OFF_NW1, 256, 256);
    pk(nw2, OFF_NW2, 256, 128);
    pk(sw1, OFF_SW1, 128, 256);
    pk(sw2, OFF_SW2, 256, 128);

    const int nAgg = N * D;
    zero_scratch<<<(nAgg + NTHR - 1) / NTHR, NTHR>>>(nAgg, N);

    edge_kernel<<<E / TM, NTHR, SMEM_BYTES>>>(sender_x, receiver_x, edge_attr, edge_index,
                                              eb1, eb2, eg, ebt, edge_out, E, N);
    node_kernel<<<N / TM, NTHR, SMEM_BYTES>>>(receiver_x, nb1, nb2, ng, nbt, receiver_out);
    sender_kernel<<<N / TM, NTHR, SMEM_BYTES>>>(sender_x, sb1, sb2, sg, sbt, sender_out);
}

// round 4
// speedup vs baseline: 2.7243x; 1.1219x over previous
#include <cuda_runtime.h>
#include <cstdint>

#define D     128
#define HID   256
#define TM    64
#define NTHR  256
#define MAXN  40000

// smem layout (floats): [0..16640) hs, [16640..25088) A/ys, [25088..33280) B dbuf
#define A_OFF    16640      // 64*260
#define SB_OFF   25088
#define SMEM_BYTES ((25088 + 8192) * 4)
#define PROJ_SMEM  ((8448 + 8192) * 4)

// Scratch (device globals: no allocations allowed)
__device__ float g_agg[(size_t)MAXN * D];
__device__ float g_cnt[MAXN];
__device__ int   g_idx_is64;
__device__ float g_Ps[(size_t)MAXN * HID];   // sender_x @ W1[0:128]
__device__ float g_Pr[(size_t)MAXN * HID];   // receiver_x @ W1[128:256]
__device__ float g_wp[294912];               // packed tf32 weights
#define OFF_W1S 0
#define OFF_W1R 32768
#define OFF_W1E 65536
#define OFF_EW2 98304
#define OFF_NW1 131072
#define OFF_NW2 196608
#define OFF_SW1 229376
#define OFF_SW2 262144

// ---------------------------------------------------------------------------
__device__ __forceinline__ uint32_t f2tf(float x) {
    uint32_t r; asm("cvt.rna.tf32.f32 %0, %1;" : "=r"(r) : "f"(x)); return r;
}
__device__ __forceinline__ float silu(float v) { return v / (1.f + __expf(-v)); }

__device__ __forceinline__ void mma8(float* c, const uint32_t* a,
                                     uint32_t b0, uint32_t b1) {
    asm volatile(
        "mma.sync.aligned.m16n8k8.row.col.f32.tf32.tf32.f32 "
        "{%0,%1,%2,%3},{%4,%5,%6,%7},{%8,%9},{%0,%1,%2,%3};"
        : "+f"(c[0]), "+f"(c[1]), "+f"(c[2]), "+f"(c[3])
        : "r"(a[0]), "r"(a[1]), "r"(a[2]), "r"(a[3]), "r"(b0), "r"(b1));
}

// ---------------------------------------------------------------------------
__global__ void detect_idx_kernel(const unsigned int* __restrict__ raw) {
    if (threadIdx.x == 0 && blockIdx.x == 0) {
        int is64 = 1;
        for (int i = 0; i < 32; ++i)
            if (raw[2 * i + 1] != 0u) { is64 = 0; break; }
        g_idx_is64 = is64;
    }
}
__device__ __forceinline__ int load_index(const void* idx, size_t pos, int n) {
    int v;
    if (g_idx_is64) v = (int)((const long long*)idx)[pos];
    else            v = ((const int*)idx)[pos];
    return v < 0 ? 0 : (v >= n ? n - 1 : v);
}

// ---------------------------------------------------------------------------
// Pack W[K][Nn] (row-major, row stride Nn) into tf32 fragment order.
// ---------------------------------------------------------------------------
__global__ void pack_kernel(const float* __restrict__ W, int dstOff, int K, int Nn) {
    const int i = blockIdx.x * blockDim.x + threadIdx.x;
    const int total = (K / 8) * (Nn / 16) * 32;
    if (i >= total) return;
    const int lane = i & 31, rest = i >> 5;
    const int NP = Nn / 16;
    const int p = rest % NP, s = rest / NP;
    const int g = lane >> 2, q = lane & 3;
    const float* r0 = W + (size_t)(s * 8 + q) * Nn + p * 16 + g;
    const float* r1 = W + (size_t)(s * 8 + q + 4) * Nn + p * 16 + g;
    float4 v;
    v.x = __uint_as_float(f2tf(r0[0]));
    v.y = __uint_as_float(f2tf(r1[0]));
    v.z = __uint_as_float(f2tf(r0[8]));
    v.w = __uint_as_float(f2tf(r1[8]));
    ((float4*)(g_wp + dstOff))[i] = v;
}

// ---------------------------------------------------------------------------
// Warp-cooperative GEMM: 8 warps = 2(M) x 4(N); per-warp tile M32 x (8*WNT).
// ---------------------------------------------------------------------------
template <int KIN, int NOUT, int WNT>
__device__ __forceinline__ void warp_gemm(const float* __restrict__ As, int astride,
                                          const float* __restrict__ Wp,
                                          float* __restrict__ sB,
                                          float* __restrict__ acc,
                                          int wm, int wn, int lane, int tid) {
    constexpr int NP    = NOUT / 16;
    constexpr int WNP   = WNT / 2;
    constexpr int SLICE = NP * 128;
    constexpr int STAGE = 2 * SLICE;      // K_TILE = 16
    constexpr int NST   = KIN / 16;
    constexpr int PF    = STAGE / (4 * NTHR);
    const int g = lane >> 2, q = lane & 3;

#pragma unroll
    for (int i = 0; i < 2 * WNT * 4; ++i) acc[i] = 0.f;

    {   // stage 0
        const float4* src = (const float4*)Wp;
        float4* dst = (float4*)sB;
#pragma unroll
        for (int i = 0; i < PF; ++i) dst[i * NTHR + tid] = src[i * NTHR + tid];
    }
    __syncthreads();

#pragma unroll 1
    for (int st = 0; st < NST; ++st) {
        float4 pf[PF];
        if (st + 1 < NST) {
            const float4* src = (const float4*)(Wp + (size_t)(st + 1) * STAGE);
#pragma unroll
            for (int i = 0; i < PF; ++i) pf[i] = src[i * NTHR + tid];
        }
        const float* bb = sB + (st & 1) * STAGE;
#pragma unroll
        for (int s2 = 0; s2 < 2; ++s2) {
            const int k0 = st * 16 + s2 * 8;
            uint32_t af[2][4];
#pragma unroll
            for (int mi = 0; mi < 2; ++mi) {
                const float* ap = As + (wm * 32 + mi * 16 + g) * astride + k0 + q;
                af[mi][0] = f2tf(ap[0]);
                af[mi][1] = f2tf(ap[8 * astride]);
                af[mi][2] = f2tf(ap[4]);
                af[mi][3] = f2tf(ap[8 * astride + 4]);
            }
#pragma unroll
            for (int p = 0; p < WNP; ++p) {
                const float4 bv =
                    *(const float4*)(bb + ((s2 * NP + wn * WNP + p) * 32 + lane) * 4);
                const uint32_t b0 = __float_as_uint(bv.x), b1 = __float_as_uint(bv.y);
                const uint32_t b2 = __float_as_uint(bv.z), b3 = __float_as_uint(bv.w);
#pragma unroll
                for (int mi = 0; mi < 2; ++mi) {
                    mma8(acc + (mi * WNT + 2 * p) * 4,     af[mi], b0, b1);
                    mma8(acc + (mi * WNT + 2 * p + 1) * 4, af[mi], b2, b3);
                }
            }
        }
        if (st + 1 < NST) {
            float4* dst = (float4*)(sB + ((st + 1) & 1) * STAGE);
#pragma unroll
            for (int i = 0; i < PF; ++i) dst[i * NTHR + tid] = pf[i];
        }
        __syncthreads();
    }
}

// GEMM1 epilogue: bias + SiLU -> hs[64][260]
__device__ __forceinline__ void epi1(const float* acc, float* hs, const float* b1s,
                                     int wm, int wn, int lane) {
    const int g = lane >> 2, q = lane & 3;
#pragma unroll
    for (int mi = 0; mi < 2; ++mi)
#pragma unroll
        for (int nt = 0; nt < 8; ++nt) {
            const float* a  = acc + (mi * 8 + nt) * 4;
            const int r0  = wm * 32 + mi * 16 + g;
            const int col = wn * 64 + nt * 8 + 2 * q;
            hs[r0 * 260 + col]           = silu(a[0] + b1s[col]);
            hs[r0 * 260 + col + 1]       = silu(a[1] + b1s[col + 1]);
            hs[(r0 + 8) * 260 + col]     = silu(a[2] + b1s[col]);
            hs[(r0 + 8) * 260 + col + 1] = silu(a[3] + b1s[col + 1]);
        }
}

// GEMM1 epilogue raw (no bias/silu) -> hs[64][260]
__device__ __forceinline__ void epi1_raw(const float* acc, float* hs,
                                         int wm, int wn, int lane) {
    const int g = lane >> 2, q = lane & 3;
#pragma unroll
    for (int mi = 0; mi < 2; ++mi)
#pragma unroll
        for (int nt = 0; nt < 8; ++nt) {
            const float* a  = acc + (mi * 8 + nt) * 4;
            const int r0  = wm * 32 + mi * 16 + g;
            const int col = wn * 64 + nt * 8 + 2 * q;
            *(float2*)&hs[r0 * 260 + col]       = make_float2(a[0], a[1]);
            *(float2*)&hs[(r0 + 8) * 260 + col] = make_float2(a[2], a[3]);
        }
}

// GEMM2 epilogue: bias -> ys[64][132]
__device__ __forceinline__ void epi2(const float* acc, float* ys, const float* b2s,
                                     int wm, int wn, int lane) {
    const int g = lane >> 2, q = lane & 3;
#pragma unroll
    for (int mi = 0; mi < 2; ++mi)
#pragma unroll
        for (int nt = 0; nt < 4; ++nt) {
            const float* a  = acc + (mi * 4 + nt) * 4;
            const int r0  = wm * 32 + mi * 16 + g;
            const int col = wn * 32 + nt * 8 + 2 * q;
            *(float2*)&ys[r0 * 132 + col]       = make_float2(a[0] + b2s[col], a[1] + b2s[col + 1]);
            *(float2*)&ys[(r0 + 8) * 132 + col] = make_float2(a[2] + b2s[col], a[3] + b2s[col + 1]);
        }
}

// ---------------------------------------------------------------------------
// Kernel P: node projections P_s = sender_x@W1s, P_r = receiver_x@W1r (raw)
// ---------------------------------------------------------------------------
__global__ __launch_bounds__(NTHR) void proj_kernel(
    const float* __restrict__ xs_, const float* __restrict__ xr_, int nb) {
    extern __shared__ float sm[];
    float* A  = sm;            // [64][132]
    float* sB = sm + 8448;

    int b = blockIdx.x;
    const float* x; const float* Wp; float* P;
    if (b < nb) { x = xs_; Wp = g_wp + OFF_W1S; P = g_Ps; }
    else        { b -= nb; x = xr_; Wp = g_wp + OFF_W1R; P = g_Pr; }

    const int tid = threadIdx.x;
    const int warp = tid >> 5, lane = tid & 31;
    const int wm = warp >> 2, wn = warp & 3;
    const int i0 = b * TM;

    for (int i = tid; i < TM * 32; i += NTHR) {
        const int m = i / 32, c4 = (i % 32) * 4;
        *(float4*)&A[m * 132 + c4] = *(const float4*)&x[(size_t)(i0 + m) * D + c4];
    }

    float acc[64];
    warp_gemm<128, 256, 8>(A, 132, Wp, sB, acc, wm, wn, lane, tid);

    const int g = lane >> 2, q = lane & 3;
#pragma unroll
    for (int mi = 0; mi < 2; ++mi)
#pragma unroll
        for (int nt = 0; nt < 8; ++nt) {
            const float* a  = acc + (mi * 8 + nt) * 4;
            const int r0  = wm * 32 + mi * 16 + g;
            const int col = wn * 64 + nt * 8 + 2 * q;
            *(float2*)&P[(size_t)(i0 + r0) * HID + col]     = make_float2(a[0], a[1]);
            *(float2*)&P[(size_t)(i0 + r0 + 8) * HID + col] = make_float2(a[2], a[3]);
        }
}

// ---------------------------------------------------------------------------
// Kernel A: edge MLP via split GEMM1 (edge part only) + gathered P_s/P_r
// ---------------------------------------------------------------------------
__global__ __launch_bounds__(NTHR) void edge_kernel(
    const float* __restrict__ edge_attr, const void* __restrict__ edge_index,
    const float* __restrict__ eb1, const float* __restrict__ eb2,
    const float* __restrict__ eg, const float* __restrict__ ebeta,
    float* __restrict__ edge_out, int E, int N) {
    extern __shared__ float sm[];
    float* hs = sm;              // [64][260]
    float* A  = sm + A_OFF;      // [64][132] (also ys after GEMM2)
    float* ys = sm + A_OFF;
    float* sB = sm + SB_OFF;
    __shared__ int s_src[TM], s_dst[TM];
    __shared__ float s_b1[HID], s_b2[D], s_g[D], s_bt[D];

    const int tid = threadIdx.x;
    const int warp = tid >> 5, lane = tid & 31;
    const int wm = warp >> 2, wn = warp & 3;
    const int e0 = blockIdx.x * TM;

    if (tid < TM)          s_src[tid]      = load_index(edge_index, e0 + tid, N);
    else if (tid < 2 * TM) s_dst[tid - TM] = load_index(edge_index, (size_t)E + e0 + tid - TM, N);
    if (tid < HID) s_b1[tid] = eb1[tid];
    if (tid < D) { s_b2[tid] = eb2[tid]; s_g[tid] = eg[tid]; s_bt[tid] = ebeta[tid]; }

    // A = edge_attr tile (contiguous rows, no indexing)
    for (int i = tid; i < TM * 32; i += NTHR) {
        const int m = i / 32, c4 = (i % 32) * 4;
        *(float4*)&A[m * 132 + c4] = *(const float4*)&edge_attr[(size_t)(e0 + m) * D + c4];
    }

    float acc1[64];
    warp_gemm<128, 256, 8>(A, 132, g_wp + OFF_W1E, sB, acc1, wm, wn, lane, tid);
    epi1_raw(acc1, hs, wm, wn, lane);
    __syncthreads();

    // hs = silu(hs + P_s[src] + P_r[dst] + b1)   (coalesced L2-resident reads)
    for (int i = tid; i < TM * 64; i += NTHR) {
        const int m = i >> 6, c4 = (i & 63) * 4;
        float4 h = *(float4*)&hs[m * 260 + c4];
        const float4 ps = __ldg((const float4*)&g_Ps[(size_t)s_src[m] * HID + c4]);
        const float4 pr = __ldg((const float4*)&g_Pr[(size_t)s_dst[m] * HID + c4]);
        h.x = silu(h.x + ps.x + pr.x + s_b1[c4 + 0]);
        h.y = silu(h.y + ps.y + pr.y + s_b1[c4 + 1]);
        h.z = silu(h.z + ps.z + pr.z + s_b1[c4 + 2]);
        h.w = silu(h.w + ps.w + pr.w + s_b1[c4 + 3]);
        *(float4*)&hs[m * 260 + c4] = h;
    }
    // (warp_gemm's internal first __syncthreads orders these writes)

    float acc2[32];
    warp_gemm<256, 128, 4>(hs, 260, g_wp + OFF_EW2, sB, acc2, wm, wn, lane, tid);
    epi2(acc2, ys, s_b2, wm, wn, lane);
    __syncthreads();

    // LN + residual + scatter, 8 rows per warp
    for (int r = warp * 8; r < warp * 8 + 8; ++r) {
        float v[4], s = 0.f, ss = 0.f;
#pragma unroll
        for (int j = 0; j < 4; ++j) {
            v[j] = ys[r * 132 + lane + 32 * j];
            s += v[j]; ss += v[j] * v[j];
        }
#pragma unroll
        for (int o = 16; o > 0; o >>= 1) {
            s  += __shfl_xor_sync(0xFFFFFFFFu, s,  o);
            ss += __shfl_xor_sync(0xFFFFFFFFu, ss, o);
        }
        const float mu  = s * (1.f / D);
        const float inv = rsqrtf(ss * (1.f / D) - mu * mu + 1e-5f);
        const int dn = s_dst[r];
        const size_t eoff = (size_t)(e0 + r) * D;
#pragma unroll
        for (int j = 0; j < 4; ++j) {
            const int c = lane + 32 * j;
            const float p = (v[j] - mu) * inv * s_g[c] + s_bt[c];
            edge_out[eoff + c] = edge_attr[eoff + c] + p;
            atomicAdd(&g_agg[(size_t)dn * D + c], p);
        }
        if (lane == 0) atomicAdd(&g_cnt[dn], 1.f);
    }
}

// ---------------------------------------------------------------------------
// Kernel B: node MLP (2D->H->D) + LN + residual
// ---------------------------------------------------------------------------
__global__ __launch_bounds__(NTHR) void node_kernel(
    const float* __restrict__ receiver_x,
    const float* __restrict__ nb1, const float* __restrict__ nb2,
    const float* __restrict__ ng, const float* __restrict__ nbeta,
    float* __restrict__ receiver_out) {
    extern __shared__ float sm[];
    float* hs = sm;              // [64][260] — A for GEMM1 also lives here
    float* A  = sm;              // [64][260] input tile (stride 260, KIN=256)
    float* ys = sm + A_OFF;
    float* sB = sm + SB_OFF;
    __shared__ float s_inv[TM];
    __shared__ float s_b1[HID], s_b2[D], s_g[D], s_bt[D];

    const int tid = threadIdx.x;
    const int warp = tid >> 5, lane = tid & 31;
    const int wm = warp >> 2, wn = warp & 3;
    const int i0 = blockIdx.x * TM;

    if (tid < TM) s_inv[tid] = 1.f / fmaxf(g_cnt[i0 + tid], 1.f);
    if (tid < HID) s_b1[tid] = nb1[tid];
    if (tid < D) { s_b2[tid] = nb2[tid]; s_g[tid] = ng[tid]; s_bt[tid] = nbeta[tid]; }
    __syncthreads();

    for (int i = tid; i < TM * 64; i += NTHR) {
        const int m = i / 64, c4 = (i % 64) * 4;
        float4 v;
        if (c4 < 128) {
            v = *(const float4*)&receiver_x[(size_t)(i0 + m) * D + c4];
        } else {
            v = *(const float4*)&g_agg[(size_t)(i0 + m) * D + (c4 - 128)];
            const float sc = s_inv[m];
            v.x *= sc; v.y *= sc; v.z *= sc; v.w *= sc;
        }
        *(float4*)&A[m * 260 + c4] = v;
    }

    // GEMM1 in-place (A == hs): write acc1 over A only AFTER full read — safe
    // because epi1 runs after warp_gemm's final __syncthreads.
    float acc1[64];
    warp_gemm<256, 256, 8>(A, 260, g_wp + OFF_NW1, sB, acc1, wm, wn, lane, tid);
    epi1(acc1, hs, s_b1, wm, wn, lane);
    __syncthreads();

    float acc2[32];
    warp_gemm<256, 128, 4>(hs, 260, g_wp + OFF_NW2, sB, acc2, wm, wn, lane, tid);
    epi2(acc2, ys, s_b2, wm, wn, lane);
    __syncthreads();

    for (int r = warp * 8; r < warp * 8 + 8; ++r) {
        float v[4], s = 0.f, ss = 0.f;
#pragma unroll
        for (int j = 0; j < 4; ++j) {
            v[j] = ys[r * 132 + lane + 32 * j];
            s += v[j]; ss += v[j] * v[j];
        }
#pragma unroll
        for (int o = 16; o > 0; o >>= 1) {
            s  += __shfl_xor_sync(0xFFFFFFFFu, s,  o);
            ss += __shfl_xor_sync(0xFFFFFFFFu, ss, o);
        }
        const float mu  = s * (1.f / D);
        const float inv = rsqrtf(ss * (1.f / D) - mu * mu + 1e-5f);
        const size_t off = (size_t)(i0 + r) * D;
#pragma unroll
        for (int j = 0; j < 4; ++j) {
            const int c = lane + 32 * j;
            const float p = (v[j] - mu) * inv * s_g[c] + s_bt[c];
            receiver_out[off + c] = receiver_x[off + c] + p;
        }
    }
}

// ---------------------------------------------------------------------------
// Kernel C: sender MLP (D->H->D) + LN + residual
// ---------------------------------------------------------------------------
__global__ __launch_bounds__(NTHR) void sender_kernel(
    const float* __restrict__ sender_x,
    const float* __restrict__ sb1, const float* __restrict__ sb2,
    const float* __restrict__ sg, const float* __restrict__ sbeta,
    float* __restrict__ sender_out) {
    extern __shared__ float sm[];
    float* hs = sm;              // [64][260]
    float* A  = sm + A_OFF;      // [64][132], ys later
    float* ys = sm + A_OFF;
    float* sB = sm + SB_OFF;
    __shared__ float s_b1[HID], s_b2[D], s_g[D], s_bt[D];

    const int tid = threadIdx.x;
    const int warp = tid >> 5, lane = tid & 31;
    const int wm = warp >> 2, wn = warp & 3;
    const int i0 = blockIdx.x * TM;

    if (tid < HID) s_b1[tid] = sb1[tid];
    if (tid < D) { s_b2[tid] = sb2[tid]; s_g[tid] = sg[tid]; s_bt[tid] = sbeta[tid]; }

    for (int i = tid; i < TM * 32; i += NTHR) {
        const int m = i / 32, c4 = (i % 32) * 4;
        *(float4*)&A[m * 132 + c4] =
            *(const float4*)&sender_x[(size_t)(i0 + m) * D + c4];
    }

    float acc1[64];
    warp_gemm<128, 256, 8>(A, 132, g_wp + OFF_SW1, sB, acc1, wm, wn, lane, tid);
    epi1(acc1, hs, s_b1, wm, wn, lane);
    __syncthreads();

    float acc2[32];
    warp_gemm<256, 128, 4>(hs, 260, g_wp + OFF_SW2, sB, acc2, wm, wn, lane, tid);
    epi2(acc2, ys, s_b2, wm, wn, lane);
    __syncthreads();

    for (int r = warp * 8; r < warp * 8 + 8; ++r) {
        float v[4], s = 0.f, ss = 0.f;
#pragma unroll
        for (int j = 0; j < 4; ++j) {
            v[j] = ys[r * 132 + lane + 32 * j];
            s += v[j]; ss += v[j] * v[j];
        }
#pragma unroll
        for (int o = 16; o > 0; o >>= 1) {
            s  += __shfl_xor_sync(0xFFFFFFFFu, s,  o);
            ss += __shfl_xor_sync(0xFFFFFFFFu, ss, o);
        }
        const float mu  = s * (1.f / D);
        const float inv = rsqrtf(ss * (1.f / D) - mu * mu + 1e-5f);
        const size_t off = (size_t)(i0 + r) * D;
#pragma unroll
        for (int j = 0; j < 4; ++j) {
            const int c = lane + 32 * j;
            const float p = (v[j] - mu) * inv * s_g[c] + s_bt[c];
            sender_out[off + c] = sender_x[off + c] + p;
        }
    }
}

// ---------------------------------------------------------------------------
__global__ void zero_scratch(int nAgg, int nCnt) {
    const int i = blockIdx.x * blockDim.x + threadIdx.x;
    if (i < nAgg) g_agg[i] = 0.f;
    if (i < nCnt) g_cnt[i] = 0.f;
}

extern "C" void kernel_launch(void* const* d_in, const int* in_sizes, int n_in,
                              void* d_out, int out_size) {
    const float* sender_x   = (const float*)d_in[0];
    const float* receiver_x = (const float*)d_in[1];
    const float* edge_attr  = (const float*)d_in[2];
    const void*  edge_index = d_in[3];
    const float* ew1 = (const float*)d_in[4];
    const float* eb1 = (const float*)d_in[5];
    const float* ew2 = (const float*)d_in[6];
    const float* eb2 = (const float*)d_in[7];
    const float* eg  = (const float*)d_in[8];
    const float* ebt = (const float*)d_in[9];
    const float* nw1 = (const float*)d_in[10];
    const float* nb1 = (const float*)d_in[11];
    const float* nw2 = (const float*)d_in[12];
    const float* nb2 = (const float*)d_in[13];
    const float* ng  = (const float*)d_in[14];
    const float* nbt = (const float*)d_in[15];
    const float* sw1 = (const float*)d_in[16];
    const float* sb1 = (const float*)d_in[17];
    const float* sw2 = (const float*)d_in[18];
    const float* sb2 = (const float*)d_in[19];
    const float* sg  = (const float*)d_in[20];
    const float* sbt = (const float*)d_in[21];

    const int N = in_sizes[0] / D;     // 40000
    const int E = in_sizes[2] / D;     // 640000

    float* out          = (float*)d_out;
    float* sender_out   = out;
    float* receiver_out = out + (size_t)N * D;
    float* edge_out     = out + (size_t)2 * N * D;

    cudaFuncSetAttribute(edge_kernel,   cudaFuncAttributeMaxDynamicSharedMemorySize, SMEM_BYTES);
    cudaFuncSetAttribute(node_kernel,   cudaFuncAttributeMaxDynamicSharedMemorySize, SMEM_BYTES);
    cudaFuncSetAttribute(sender_kernel, cudaFuncAttributeMaxDynamicSharedMemorySize, SMEM_BYTES);
    cudaFuncSetAttribute(proj_kernel,   cudaFuncAttributeMaxDynamicSharedMemorySize, PROJ_SMEM);

    detect_idx_kernel<<<1, 32>>>((const unsigned int*)edge_index);

    // pack weights into tf32 fragment order (W1 split into 3 K=128 parts)
    auto pk = [](const float* w, int off, int K, int Nn) {
        const int tot = (K / 8) * (Nn / 16) * 32;
        pack_kernel<<<(tot + 255) / 256, 256>>>(w, off, K, Nn);
    };
    pk(ew1,             OFF_W1S, 128, 256);
    pk(ew1 + 128 * HID, OFF_W1R, 128, 256);
    pk(ew1 + 256 * HID, OFF_W1E, 128, 256);
    pk(ew2, OFF_EW2, 256, 128);
    pk(nw1, OFF_NW1, 256, 256);
    pk(nw2, OFF_NW2, 256, 128);
    pk(sw1, OFF_SW1, 128, 256);
    pk(sw2, OFF_SW2, 256, 128);

    const int nAgg = N * D;
    zero_scratch<<<(nAgg + NTHR - 1) / NTHR, NTHR>>>(nAgg, N);

    const int nb = N / TM;             // 625
    proj_kernel<<<2 * nb, NTHR, PROJ_SMEM>>>(sender_x, receiver_x, nb);

    edge_kernel<<<E / TM, NTHR, SMEM_BYTES>>>(edge_attr, edge_index,
                                              eb1, eb2, eg, ebt, edge_out, E, N);
    node_kernel<<<N / TM, NTHR, SMEM_BYTES>>>(receiver_x, nb1, nb2, ng, nbt, receiver_out);
    sender_kernel<<<N / TM, NTHR, SMEM_BYTES>>>(sender_x, sb1, sb2, sg, sbt, sender_out);
}

// round 5
// speedup vs baseline: 3.1882x; 1.1703x over previous
#include <cuda_runtime.h>
#include <cstdint>

#define D     128
#define HID   256
#define TM    64
#define NTHR  512
#define MAXN  40000

// smem layout (floats): [0..16640) hs, [16640..25088) A/ys, [25088..33280) B dbuf
#define A_OFF    16640      // 64*260
#define SB_OFF   25088
#define SMEM_BYTES ((25088 + 8192) * 4)
#define PROJ_SMEM  ((8448 + 8192) * 4)

// Scratch (device globals: no allocations allowed)
__device__ float g_agg[(size_t)MAXN * D];
__device__ float g_cnt[MAXN];
__device__ int   g_idx_is64;
__device__ float g_Ps[(size_t)MAXN * HID];   // sender_x @ W1[0:128]
__device__ float g_Pr[(size_t)MAXN * HID];   // receiver_x @ W1[128:256]
__device__ float g_wp[294912];               // packed tf32 weights
#define OFF_W1S 0
#define OFF_W1R 32768
#define OFF_W1E 65536
#define OFF_EW2 98304
#define OFF_NW1 131072
#define OFF_NW2 196608
#define OFF_SW1 229376
#define OFF_SW2 262144

// ---------------------------------------------------------------------------
__device__ __forceinline__ uint32_t f2tf(float x) {
    uint32_t r; asm("cvt.rna.tf32.f32 %0, %1;" : "=r"(r) : "f"(x)); return r;
}
__device__ __forceinline__ float silu(float v) { return v / (1.f + __expf(-v)); }

__device__ __forceinline__ void mma8(float* c, const uint32_t* a,
                                     uint32_t b0, uint32_t b1) {
    asm volatile(
        "mma.sync.aligned.m16n8k8.row.col.f32.tf32.tf32.f32 "
        "{%0,%1,%2,%3},{%4,%5,%6,%7},{%8,%9},{%0,%1,%2,%3};"
        : "+f"(c[0]), "+f"(c[1]), "+f"(c[2]), "+f"(c[3])
        : "r"(a[0]), "r"(a[1]), "r"(a[2]), "r"(a[3]), "r"(b0), "r"(b1));
}

// ---------------------------------------------------------------------------
__global__ void detect_idx_kernel(const unsigned int* __restrict__ raw) {
    if (threadIdx.x == 0 && blockIdx.x == 0) {
        int is64 = 1;
        for (int i = 0; i < 32; ++i)
            if (raw[2 * i + 1] != 0u) { is64 = 0; break; }
        g_idx_is64 = is64;
    }
}
__device__ __forceinline__ int load_index(const void* idx, size_t pos, int n) {
    int v;
    if (g_idx_is64) v = (int)((const long long*)idx)[pos];
    else            v = ((const int*)idx)[pos];
    return v < 0 ? 0 : (v >= n ? n - 1 : v);
}

// ---------------------------------------------------------------------------
// Pack all weight matrices into tf32 fragment order (single launch).
// ---------------------------------------------------------------------------
__global__ void pack_all_kernel(const float* __restrict__ ew1, const float* __restrict__ ew2,
                                const float* __restrict__ nw1, const float* __restrict__ nw2,
                                const float* __restrict__ sw1, const float* __restrict__ sw2) {
    int b = blockIdx.x;
    const float* W; int off, K, Nn;
    if      (b < 32)  { W = ew1;             off = OFF_W1S; K = 128; Nn = 256; }
    else if (b < 64)  { W = ew1 + 128 * HID; off = OFF_W1R; K = 128; Nn = 256; b -= 32; }
    else if (b < 96)  { W = ew1 + 256 * HID; off = OFF_W1E; K = 128; Nn = 256; b -= 64; }
    else if (b < 128) { W = ew2;             off = OFF_EW2; K = 256; Nn = 128; b -= 96; }
    else if (b < 192) { W = nw1;             off = OFF_NW1; K = 256; Nn = 256; b -= 128; }
    else if (b < 224) { W = nw2;             off = OFF_NW2; K = 256; Nn = 128; b -= 192; }
    else if (b < 256) { W = sw1;             off = OFF_SW1; K = 128; Nn = 256; b -= 224; }
    else              { W = sw2;             off = OFF_SW2; K = 256; Nn = 128; b -= 256; }
    const int i = b * blockDim.x + threadIdx.x;
    const int total = (K / 8) * (Nn / 16) * 32;
    if (i >= total) return;
    const int lane = i & 31, rest = i >> 5;
    const int NP = Nn / 16;
    const int p = rest % NP, s = rest / NP;
    const int g = lane >> 2, q = lane & 3;
    const float* r0 = W + (size_t)(s * 8 + q) * Nn + p * 16 + g;
    const float* r1 = W + (size_t)(s * 8 + q + 4) * Nn + p * 16 + g;
    float4 v;
    v.x = __uint_as_float(f2tf(r0[0]));
    v.y = __uint_as_float(f2tf(r1[0]));
    v.z = __uint_as_float(f2tf(r0[8]));
    v.w = __uint_as_float(f2tf(r1[8]));
    ((float4*)(g_wp + off))[i] = v;
}

// ---------------------------------------------------------------------------
// Warp-cooperative GEMM: 16 warps = 4(M) x 4(N); per-warp tile M16 x (8*WNT).
// acc[nt*4 + i], nt < WNT.
// ---------------------------------------------------------------------------
template <int KIN, int NOUT, int WNT>
__device__ __forceinline__ void warp_gemm(const float* __restrict__ As, int astride,
                                          const float* __restrict__ Wp,
                                          float* __restrict__ sB,
                                          float* __restrict__ acc,
                                          int wm, int wn, int lane, int tid) {
    constexpr int NP    = NOUT / 16;
    constexpr int WNP   = WNT / 2;
    constexpr int SLICE = NP * 128;
    constexpr int STAGE = 2 * SLICE;      // K_TILE = 16
    constexpr int NST   = KIN / 16;
    constexpr int PF    = STAGE / (4 * NTHR);
    const int g = lane >> 2, q = lane & 3;

#pragma unroll
    for (int i = 0; i < WNT * 4; ++i) acc[i] = 0.f;

    {   // stage 0
        const float4* src = (const float4*)Wp;
        float4* dst = (float4*)sB;
#pragma unroll
        for (int i = 0; i < PF; ++i) dst[i * NTHR + tid] = src[i * NTHR + tid];
    }
    __syncthreads();

#pragma unroll 1
    for (int st = 0; st < NST; ++st) {
        float4 pf[PF];
        if (st + 1 < NST) {
            const float4* src = (const float4*)(Wp + (size_t)(st + 1) * STAGE);
#pragma unroll
            for (int i = 0; i < PF; ++i) pf[i] = src[i * NTHR + tid];
        }
        const float* bb = sB + (st & 1) * STAGE;
#pragma unroll
        for (int s2 = 0; s2 < 2; ++s2) {
            const int k0 = st * 16 + s2 * 8;
            uint32_t af[4];
            const float* ap = As + (wm * 16 + g) * astride + k0 + q;
            af[0] = f2tf(ap[0]);
            af[1] = f2tf(ap[8 * astride]);
            af[2] = f2tf(ap[4]);
            af[3] = f2tf(ap[8 * astride + 4]);
#pragma unroll
            for (int p = 0; p < WNP; ++p) {
                const float4 bv =
                    *(const float4*)(bb + ((s2 * NP + wn * WNP + p) * 32 + lane) * 4);
                mma8(acc + (2 * p) * 4,     af, __float_as_uint(bv.x), __float_as_uint(bv.y));
                mma8(acc + (2 * p + 1) * 4, af, __float_as_uint(bv.z), __float_as_uint(bv.w));
            }
        }
        if (st + 1 < NST) {
            float4* dst = (float4*)(sB + ((st + 1) & 1) * STAGE);
#pragma unroll
            for (int i = 0; i < PF; ++i) dst[i * NTHR + tid] = pf[i];
        }
        __syncthreads();
    }
}

// GEMM1 epilogue: bias + SiLU -> hs[64][260]   (WNT=8)
__device__ __forceinline__ void epi1(const float* acc, float* hs, const float* b1s,
                                     int wm, int wn, int lane) {
    const int g = lane >> 2, q = lane & 3;
#pragma unroll
    for (int nt = 0; nt < 8; ++nt) {
        const float* a  = acc + nt * 4;
        const int r0  = wm * 16 + g;
        const int col = wn * 64 + nt * 8 + 2 * q;
        hs[r0 * 260 + col]           = silu(a[0] + b1s[col]);
        hs[r0 * 260 + col + 1]       = silu(a[1] + b1s[col + 1]);
        hs[(r0 + 8) * 260 + col]     = silu(a[2] + b1s[col]);
        hs[(r0 + 8) * 260 + col + 1] = silu(a[3] + b1s[col + 1]);
    }
}

// GEMM1 epilogue raw (no bias/silu) -> hs[64][260]
__device__ __forceinline__ void epi1_raw(const float* acc, float* hs,
                                         int wm, int wn, int lane) {
    const int g = lane >> 2, q = lane & 3;
#pragma unroll
    for (int nt = 0; nt < 8; ++nt) {
        const float* a  = acc + nt * 4;
        const int r0  = wm * 16 + g;
        const int col = wn * 64 + nt * 8 + 2 * q;
        *(float2*)&hs[r0 * 260 + col]       = make_float2(a[0], a[1]);
        *(float2*)&hs[(r0 + 8) * 260 + col] = make_float2(a[2], a[3]);
    }
}

// GEMM2 epilogue: bias -> ys[64][132]   (WNT=4)
__device__ __forceinline__ void epi2(const float* acc, float* ys, const float* b2s,
                                     int wm, int wn, int lane) {
    const int g = lane >> 2, q = lane & 3;
#pragma unroll
    for (int nt = 0; nt < 4; ++nt) {
        const float* a  = acc + nt * 4;
        const int r0  = wm * 16 + g;
        const int col = wn * 32 + nt * 8 + 2 * q;
        *(float2*)&ys[r0 * 132 + col]       = make_float2(a[0] + b2s[col], a[1] + b2s[col + 1]);
        *(float2*)&ys[(r0 + 8) * 132 + col] = make_float2(a[2] + b2s[col], a[3] + b2s[col + 1]);
    }
}

// ---------------------------------------------------------------------------
// Kernel P: node projections P_s = sender_x@W1s, P_r = receiver_x@W1r (raw)
// ---------------------------------------------------------------------------
__global__ __launch_bounds__(NTHR) void proj_kernel(
    const float* __restrict__ xs_, const float* __restrict__ xr_, int nb) {
    extern __shared__ float sm[];
    float* A  = sm;            // [64][132]
    float* sB = sm + 8448;

    int b = blockIdx.x;
    const float* x; const float* Wp; float* P;
    if (b < nb) { x = xs_; Wp = g_wp + OFF_W1S; P = g_Ps; }
    else        { b -= nb; x = xr_; Wp = g_wp + OFF_W1R; P = g_Pr; }

    const int tid = threadIdx.x;
    const int warp = tid >> 5, lane = tid & 31;
    const int wm = warp >> 2, wn = warp & 3;
    const int i0 = b * TM;

    for (int i = tid; i < TM * 32; i += NTHR) {
        const int m = i / 32, c4 = (i % 32) * 4;
        *(float4*)&A[m * 132 + c4] = *(const float4*)&x[(size_t)(i0 + m) * D + c4];
    }

    float acc[32];
    warp_gemm<128, 256, 8>(A, 132, Wp, sB, acc, wm, wn, lane, tid);

    const int g = lane >> 2, q = lane & 3;
#pragma unroll
    for (int nt = 0; nt < 8; ++nt) {
        const float* a  = acc + nt * 4;
        const int r0  = wm * 16 + g;
        const int col = wn * 64 + nt * 8 + 2 * q;
        *(float2*)&P[(size_t)(i0 + r0) * HID + col]     = make_float2(a[0], a[1]);
        *(float2*)&P[(size_t)(i0 + r0 + 8) * HID + col] = make_float2(a[2], a[3]);
    }
}

// ---------------------------------------------------------------------------
// Kernel A: edge MLP via split GEMM1 (edge part only) + gathered P_s/P_r
// ---------------------------------------------------------------------------
__global__ __launch_bounds__(NTHR) void edge_kernel(
    const float* __restrict__ edge_attr, const void* __restrict__ edge_index,
    const float* __restrict__ eb1, const float* __restrict__ eb2,
    const float* __restrict__ eg, const float* __restrict__ ebeta,
    float* __restrict__ edge_out, int E, int N) {
    extern __shared__ float sm[];
    float* hs = sm;              // [64][260]
    float* A  = sm + A_OFF;      // [64][132] (also ys after GEMM2)
    float* ys = sm + A_OFF;
    float* sB = sm + SB_OFF;
    __shared__ int s_src[TM], s_dst[TM];
    __shared__ float s_b1[HID], s_b2[D], s_g[D], s_bt[D];

    const int tid = threadIdx.x;
    const int warp = tid >> 5, lane = tid & 31;
    const int wm = warp >> 2, wn = warp & 3;
    const int e0 = blockIdx.x * TM;

    if (tid < TM)          s_src[tid]      = load_index(edge_index, e0 + tid, N);
    else if (tid < 2 * TM) s_dst[tid - TM] = load_index(edge_index, (size_t)E + e0 + tid - TM, N);
    if (tid < HID) s_b1[tid] = eb1[tid];
    if (tid < D) { s_b2[tid] = eb2[tid]; s_g[tid] = eg[tid]; s_bt[tid] = ebeta[tid]; }

    // A = edge_attr tile (contiguous rows, no indexing)
    for (int i = tid; i < TM * 32; i += NTHR) {
        const int m = i / 32, c4 = (i % 32) * 4;
        *(float4*)&A[m * 132 + c4] = *(const float4*)&edge_attr[(size_t)(e0 + m) * D + c4];
    }

    float acc1[32];
    warp_gemm<128, 256, 8>(A, 132, g_wp + OFF_W1E, sB, acc1, wm, wn, lane, tid);
    epi1_raw(acc1, hs, wm, wn, lane);
    __syncthreads();

    // hs = silu(hs + P_s[src] + P_r[dst] + b1)   (coalesced L2-resident reads)
    for (int i = tid; i < TM * 64; i += NTHR) {
        const int m = i >> 6, c4 = (i & 63) * 4;
        float4 h = *(float4*)&hs[m * 260 + c4];
        const float4 ps = __ldg((const float4*)&g_Ps[(size_t)s_src[m] * HID + c4]);
        const float4 pr = __ldg((const float4*)&g_Pr[(size_t)s_dst[m] * HID + c4]);
        h.x = silu(h.x + ps.x + pr.x + s_b1[c4 + 0]);
        h.y = silu(h.y + ps.y + pr.y + s_b1[c4 + 1]);
        h.z = silu(h.z + ps.z + pr.z + s_b1[c4 + 2]);
        h.w = silu(h.w + ps.w + pr.w + s_b1[c4 + 3]);
        *(float4*)&hs[m * 260 + c4] = h;
    }
    // (warp_gemm's internal first __syncthreads orders these writes)

    float acc2[16];
    warp_gemm<256, 128, 4>(hs, 260, g_wp + OFF_EW2, sB, acc2, wm, wn, lane, tid);
    epi2(acc2, ys, s_b2, wm, wn, lane);
    __syncthreads();

    // LN + residual + scatter, 4 rows per warp
    for (int r = warp * 4; r < warp * 4 + 4; ++r) {
        float v[4], s = 0.f, ss = 0.f;
#pragma unroll
        for (int j = 0; j < 4; ++j) {
            v[j] = ys[r * 132 + lane + 32 * j];
            s += v[j]; ss += v[j] * v[j];
        }
#pragma unroll
        for (int o = 16; o > 0; o >>= 1) {
            s  += __shfl_xor_sync(0xFFFFFFFFu, s,  o);
            ss += __shfl_xor_sync(0xFFFFFFFFu, ss, o);
        }
        const float mu  = s * (1.f / D);
        const float inv = rsqrtf(ss * (1.f / D) - mu * mu + 1e-5f);
        const int dn = s_dst[r];
        const size_t eoff = (size_t)(e0 + r) * D;
#pragma unroll
        for (int j = 0; j < 4; ++j) {
            const int c = lane + 32 * j;
            const float p = (v[j] - mu) * inv * s_g[c] + s_bt[c];
            edge_out[eoff + c] = edge_attr[eoff + c] + p;
            atomicAdd(&g_agg[(size_t)dn * D + c], p);
        }
        if (lane == 0) atomicAdd(&g_cnt[dn], 1.f);
    }
}

// ---------------------------------------------------------------------------
// Kernel B: node MLP (2D->H->D) + LN + residual
// ---------------------------------------------------------------------------
__global__ __launch_bounds__(NTHR) void node_kernel(
    const float* __restrict__ receiver_x,
    const float* __restrict__ nb1, const float* __restrict__ nb2,
    const float* __restrict__ ng, const float* __restrict__ nbeta,
    float* __restrict__ receiver_out) {
    extern __shared__ float sm[];
    float* hs = sm;              // [64][260] — A for GEMM1 also lives here
    float* A  = sm;
    float* ys = sm + A_OFF;
    float* sB = sm + SB_OFF;
    __shared__ float s_inv[TM];
    __shared__ float s_b1[HID], s_b2[D], s_g[D], s_bt[D];

    const int tid = threadIdx.x;
    const int warp = tid >> 5, lane = tid & 31;
    const int wm = warp >> 2, wn = warp & 3;
    const int i0 = blockIdx.x * TM;

    if (tid < TM) s_inv[tid] = 1.f / fmaxf(g_cnt[i0 + tid], 1.f);
    if (tid < HID) s_b1[tid] = nb1[tid];
    if (tid < D) { s_b2[tid] = nb2[tid]; s_g[tid] = ng[tid]; s_bt[tid] = nbeta[tid]; }
    __syncthreads();

    for (int i = tid; i < TM * 64; i += NTHR) {
        const int m = i / 64, c4 = (i % 64) * 4;
        float4 v;
        if (c4 < 128) {
            v = *(const float4*)&receiver_x[(size_t)(i0 + m) * D + c4];
        } else {
            v = *(const float4*)&g_agg[(size_t)(i0 + m) * D + (c4 - 128)];
            const float sc = s_inv[m];
            v.x *= sc; v.y *= sc; v.z *= sc; v.w *= sc;
        }
        *(float4*)&A[m * 260 + c4] = v;
    }

    float acc1[32];
    warp_gemm<256, 256, 8>(A, 260, g_wp + OFF_NW1, sB, acc1, wm, wn, lane, tid);
    epi1(acc1, hs, s_b1, wm, wn, lane);
    __syncthreads();

    float acc2[16];
    warp_gemm<256, 128, 4>(hs, 260, g_wp + OFF_NW2, sB, acc2, wm, wn, lane, tid);
    epi2(acc2, ys, s_b2, wm, wn, lane);
    __syncthreads();

    for (int r = warp * 4; r < warp * 4 + 4; ++r) {
        float v[4], s = 0.f, ss = 0.f;
#pragma unroll
        for (int j = 0; j < 4; ++j) {
            v[j] = ys[r * 132 + lane + 32 * j];
            s += v[j]; ss += v[j] * v[j];
        }
#pragma unroll
        for (int o = 16; o > 0; o >>= 1) {
            s  += __shfl_xor_sync(0xFFFFFFFFu, s,  o);
            ss += __shfl_xor_sync(0xFFFFFFFFu, ss, o);
        }
        const float mu  = s * (1.f / D);
        const float inv = rsqrtf(ss * (1.f / D) - mu * mu + 1e-5f);
        const size_t off = (size_t)(i0 + r) * D;
#pragma unroll
        for (int j = 0; j < 4; ++j) {
            const int c = lane + 32 * j;
            const float p = (v[j] - mu) * inv * s_g[c] + s_bt[c];
            receiver_out[off + c] = receiver_x[off + c] + p;
        }
    }
}

// ---------------------------------------------------------------------------
// Kernel C: sender MLP (D->H->D) + LN + residual
// ---------------------------------------------------------------------------
__global__ __launch_bounds__(NTHR) void sender_kernel(
    const float* __restrict__ sender_x,
    const float* __restrict__ sb1, const float* __restrict__ sb2,
    const float* __restrict__ sg, const float* __restrict__ sbeta,
    float* __restrict__ sender_out) {
    extern __shared__ float sm[];
    float* hs = sm;              // [64][260]
    float* A  = sm + A_OFF;      // [64][132], ys later
    float* ys = sm + A_OFF;
    float* sB = sm + SB_OFF;
    __shared__ float s_b1[HID], s_b2[D], s_g[D], s_bt[D];

    const int tid = threadIdx.x;
    const int warp = tid >> 5, lane = tid & 31;
    const int wm = warp >> 2, wn = warp & 3;
    const int i0 = blockIdx.x * TM;

    if (tid < HID) s_b1[tid] = sb1[tid];
    if (tid < D) { s_b2[tid] = sb2[tid]; s_g[tid] = sg[tid]; s_bt[tid] = sbeta[tid]; }

    for (int i = tid; i < TM * 32; i += NTHR) {
        const int m = i / 32, c4 = (i % 32) * 4;
        *(float4*)&A[m * 132 + c4] =
            *(const float4*)&sender_x[(size_t)(i0 + m) * D + c4];
    }

    float acc1[32];
    warp_gemm<128, 256, 8>(A, 132, g_wp + OFF_SW1, sB, acc1, wm, wn, lane, tid);
    epi1(acc1, hs, s_b1, wm, wn, lane);
    __syncthreads();

    float acc2[16];
    warp_gemm<256, 128, 4>(hs, 260, g_wp + OFF_SW2, sB, acc2, wm, wn, lane, tid);
    epi2(acc2, ys, s_b2, wm, wn, lane);
    __syncthreads();

    for (int r = warp * 4; r < warp * 4 + 4; ++r) {
        float v[4], s = 0.f, ss = 0.f;
#pragma unroll
        for (int j = 0; j < 4; ++j) {
            v[j] = ys[r * 132 + lane + 32 * j];
            s += v[j]; ss += v[j] * v[j];
        }
#pragma unroll
        for (int o = 16; o > 0; o >>= 1) {
            s  += __shfl_xor_sync(0xFFFFFFFFu, s,  o);
            ss += __shfl_xor_sync(0xFFFFFFFFu, ss, o);
        }
        const float mu  = s * (1.f / D);
        const float inv = rsqrtf(ss * (1.f / D) - mu * mu + 1e-5f);
        const size_t off = (size_t)(i0 + r) * D;
#pragma unroll
        for (int j = 0; j < 4; ++j) {
            const int c = lane + 32 * j;
            const float p = (v[j] - mu) * inv * s_g[c] + s_bt[c];
            sender_out[off + c] = sender_x[off + c] + p;
        }
    }
}

// ---------------------------------------------------------------------------
__global__ void zero_agg_kernel(int nAgg) {
    const int i = blockIdx.x * blockDim.x + threadIdx.x;
    if (i < nAgg) g_agg[i] = 0.f;
}
__global__ void zero_cnt_kernel(int nCnt) {
    const int i = blockIdx.x * blockDim.x + threadIdx.x;
    if (i < nCnt) g_cnt[i] = 0.f;
}

extern "C" void kernel_launch(void* const* d_in, const int* in_sizes, int n_in,
                              void* d_out, int out_size) {
    const float* sender_x   = (const float*)d_in[0];
    const float* receiver_x = (const float*)d_in[1];
    const float* edge_attr  = (const float*)d_in[2];
    const void*  edge_index = d_in[3];
    const float* ew1 = (const float*)d_in[4];
    const float* eb1 = (const float*)d_in[5];
    const float* ew2 = (const float*)d_in[6];
    const float* eb2 = (const float*)d_in[7];
    const float* eg  = (const float*)d_in[8];
    const float* ebt = (const float*)d_in[9];
    const float* nw1 = (const float*)d_in[10];
    const float* nb1 = (const float*)d_in[11];
    const float* nw2 = (const float*)d_in[12];
    const float* nb2 = (const float*)d_in[13];
    const float* ng  = (const float*)d_in[14];
    const float* nbt = (const float*)d_in[15];
    const float* sw1 = (const float*)d_in[16];
    const float* sb1 = (const float*)d_in[17];
    const float* sw2 = (const float*)d_in[18];
    const float* sb2 = (const float*)d_in[19];
    const float* sg  = (const float*)d_in[20];
    const float* sbt = (const float*)d_in[21];

    const int N = in_sizes[0] / D;     // 40000
    const int E = in_sizes[2] / D;     // 640000

    float* out          = (float*)d_out;
    float* sender_out   = out;
    float* receiver_out = out + (size_t)N * D;
    float* edge_out     = out + (size_t)2 * N * D;

    cudaFuncSetAttribute(edge_kernel,   cudaFuncAttributeMaxDynamicSharedMemorySize, SMEM_BYTES);
    cudaFuncSetAttribute(node_kernel,   cudaFuncAttributeMaxDynamicSharedMemorySize, SMEM_BYTES);
    cudaFuncSetAttribute(sender_kernel, cudaFuncAttributeMaxDynamicSharedMemorySize, SMEM_BYTES);
    cudaFuncSetAttribute(proj_kernel,   cudaFuncAttributeMaxDynamicSharedMemorySize, PROJ_SMEM);

    const int nAgg = N * D;
    const int nb = N / TM;             // 625

    // Launch order chosen so edge_kernel is launch #6 (ncu -s 5 -c 1 captures it).
    detect_idx_kernel<<<1, 32>>>((const unsigned int*)edge_index);            // 1
    pack_all_kernel<<<288, 256>>>(ew1, ew2, nw1, nw2, sw1, sw2);              // 2
    zero_agg_kernel<<<(nAgg + 511) / 512, 512>>>(nAgg);                       // 3
    zero_cnt_kernel<<<(N + 511) / 512, 512>>>(N);                             // 4
    proj_kernel<<<2 * nb, NTHR, PROJ_SMEM>>>(sender_x, receiver_x, nb);       // 5
    edge_kernel<<<E / TM, NTHR, SMEM_BYTES>>>(edge_attr, edge_index,          // 6
                                              eb1, eb2, eg, ebt, edge_out, E, N);
    node_kernel<<<N / TM, NTHR, SMEM_BYTES>>>(receiver_x, nb1, nb2, ng, nbt, receiver_out);
    sender_kernel<<<N / TM, NTHR, SMEM_BYTES>>>(sender_x, sb1, sb2, sg, sbt, sender_out);
}

// round 6
// speedup vs baseline: 3.5436x; 1.1115x over previous
#include <cuda_runtime.h>
#include <cstdint>

#define D     128
#define HID   256
#define TM    32
#define NTHR  256
#define MAXN  40000

// smem layout (floats): [0..8320) hs, [8320..12544) A/ys, [12544..20736) B dbuf
#define A_OFF    8320       // 32*260
#define SB_OFF   12544
#define SMEM_BYTES ((12544 + 8192) * 4)
#define PROJ_SMEM  ((4224 + 8192) * 4)

// Scratch (device globals: no allocations allowed)
__device__ float g_agg[(size_t)MAXN * D];
__device__ float g_cnt[MAXN];
__device__ int   g_idx_is64;
__device__ float g_Ps[(size_t)MAXN * HID];   // sender_x @ W1[0:128]
__device__ float g_Pr[(size_t)MAXN * HID];   // receiver_x @ W1[128:256]
__device__ float g_wp[294912];               // packed tf32 weights
#define OFF_W1S 0
#define OFF_W1R 32768
#define OFF_W1E 65536
#define OFF_EW2 98304
#define OFF_NW1 131072
#define OFF_NW2 196608
#define OFF_SW1 229376
#define OFF_SW2 262144

// ---------------------------------------------------------------------------
__device__ __forceinline__ uint32_t f2tf(float x) {
    uint32_t r; asm("cvt.rna.tf32.f32 %0, %1;" : "=r"(r) : "f"(x)); return r;
}
__device__ __forceinline__ float silu(float v) { return v / (1.f + __expf(-v)); }

__device__ __forceinline__ void mma8(float* c, const uint32_t* a,
                                     uint32_t b0, uint32_t b1) {
    asm volatile(
        "mma.sync.aligned.m16n8k8.row.col.f32.tf32.tf32.f32 "
        "{%0,%1,%2,%3},{%4,%5,%6,%7},{%8,%9},{%0,%1,%2,%3};"
        : "+f"(c[0]), "+f"(c[1]), "+f"(c[2]), "+f"(c[3])
        : "r"(a[0]), "r"(a[1]), "r"(a[2]), "r"(a[3]), "r"(b0), "r"(b1));
}

// ---------------------------------------------------------------------------
__global__ void detect_idx_kernel(const unsigned int* __restrict__ raw) {
    if (threadIdx.x == 0 && blockIdx.x == 0) {
        int is64 = 1;
        for (int i = 0; i < 32; ++i)
            if (raw[2 * i + 1] != 0u) { is64 = 0; break; }
        g_idx_is64 = is64;
    }
}
__device__ __forceinline__ int load_index(const void* idx, size_t pos, int n) {
    int v;
    if (g_idx_is64) v = (int)((const long long*)idx)[pos];
    else            v = ((const int*)idx)[pos];
    return v < 0 ? 0 : (v >= n ? n - 1 : v);
}

// ---------------------------------------------------------------------------
// Pack all weight matrices into tf32 fragment order (single launch).
// ---------------------------------------------------------------------------
__global__ void pack_all_kernel(const float* __restrict__ ew1, const float* __restrict__ ew2,
                                const float* __restrict__ nw1, const float* __restrict__ nw2,
                                const float* __restrict__ sw1, const float* __restrict__ sw2) {
    int b = blockIdx.x;
    const float* W; int off, K, Nn;
    if      (b < 32)  { W = ew1;             off = OFF_W1S; K = 128; Nn = 256; }
    else if (b < 64)  { W = ew1 + 128 * HID; off = OFF_W1R; K = 128; Nn = 256; b -= 32; }
    else if (b < 96)  { W = ew1 + 256 * HID; off = OFF_W1E; K = 128; Nn = 256; b -= 64; }
    else if (b < 128) { W = ew2;             off = OFF_EW2; K = 256; Nn = 128; b -= 96; }
    else if (b < 192) { W = nw1;             off = OFF_NW1; K = 256; Nn = 256; b -= 128; }
    else if (b < 224) { W = nw2;             off = OFF_NW2; K = 256; Nn = 128; b -= 192; }
    else if (b < 256) { W = sw1;             off = OFF_SW1; K = 128; Nn = 256; b -= 224; }
    else              { W = sw2;             off = OFF_SW2; K = 256; Nn = 128; b -= 256; }
    const int i = b * blockDim.x + threadIdx.x;
    const int total = (K / 8) * (Nn / 16) * 32;
    if (i >= total) return;
    const int lane = i & 31, rest = i >> 5;
    const int NP = Nn / 16;
    const int p = rest % NP, s = rest / NP;
    const int g = lane >> 2, q = lane & 3;
    const float* r0 = W + (size_t)(s * 8 + q) * Nn + p * 16 + g;
    const float* r1 = W + (size_t)(s * 8 + q + 4) * Nn + p * 16 + g;
    float4 v;
    v.x = __uint_as_float(f2tf(r0[0]));
    v.y = __uint_as_float(f2tf(r1[0]));
    v.z = __uint_as_float(f2tf(r0[8]));
    v.w = __uint_as_float(f2tf(r1[8]));
    ((float4*)(g_wp + off))[i] = v;
}

// ---------------------------------------------------------------------------
// Warp-cooperative GEMM: 8 warps = 2(M) x 4(N); per-warp tile M16 x (8*WNT).
// ---------------------------------------------------------------------------
template <int KIN, int NOUT, int WNT>
__device__ __forceinline__ void warp_gemm(const float* __restrict__ As, int astride,
                                          const float* __restrict__ Wp,
                                          float* __restrict__ sB,
                                          float* __restrict__ acc,
                                          int wm, int wn, int lane, int tid) {
    constexpr int NP    = NOUT / 16;
    constexpr int WNP   = WNT / 2;
    constexpr int SLICE = NP * 128;
    constexpr int STAGE = 2 * SLICE;      // K_TILE = 16
    constexpr int NST   = KIN / 16;
    constexpr int PF    = STAGE / (4 * NTHR);
    const int g = lane >> 2, q = lane & 3;

#pragma unroll
    for (int i = 0; i < WNT * 4; ++i) acc[i] = 0.f;

    {   // stage 0
        const float4* src = (const float4*)Wp;
        float4* dst = (float4*)sB;
#pragma unroll
        for (int i = 0; i < PF; ++i) dst[i * NTHR + tid] = src[i * NTHR + tid];
    }
    __syncthreads();

#pragma unroll 1
    for (int st = 0; st < NST; ++st) {
        float4 pf[PF];
        if (st + 1 < NST) {
            const float4* src = (const float4*)(Wp + (size_t)(st + 1) * STAGE);
#pragma unroll
            for (int i = 0; i < PF; ++i) pf[i] = src[i * NTHR + tid];
        }
        const float* bb = sB + (st & 1) * STAGE;
#pragma unroll
        for (int s2 = 0; s2 < 2; ++s2) {
            const int k0 = st * 16 + s2 * 8;
            uint32_t af[4];
            const float* ap = As + (wm * 16 + g) * astride + k0 + q;
            af[0] = f2tf(ap[0]);
            af[1] = f2tf(ap[8 * astride]);
            af[2] = f2tf(ap[4]);
            af[3] = f2tf(ap[8 * astride + 4]);
#pragma unroll
            for (int p = 0; p < WNP; ++p) {
                const float4 bv =
                    *(const float4*)(bb + ((s2 * NP + wn * WNP + p) * 32 + lane) * 4);
                mma8(acc + (2 * p) * 4,     af, __float_as_uint(bv.x), __float_as_uint(bv.y));
                mma8(acc + (2 * p + 1) * 4, af, __float_as_uint(bv.z), __float_as_uint(bv.w));
            }
        }
        if (st + 1 < NST) {
            float4* dst = (float4*)(sB + ((st + 1) & 1) * STAGE);
#pragma unroll
            for (int i = 0; i < PF; ++i) dst[i * NTHR + tid] = pf[i];
        }
        __syncthreads();
    }
}

// GEMM1 epilogue: bias + SiLU -> hs[32][260]   (WNT=8)
__device__ __forceinline__ void epi1(const float* acc, float* hs, const float* b1s,
                                     int wm, int wn, int lane) {
    const int g = lane >> 2, q = lane & 3;
#pragma unroll
    for (int nt = 0; nt < 8; ++nt) {
        const float* a  = acc + nt * 4;
        const int r0  = wm * 16 + g;
        const int col = wn * 64 + nt * 8 + 2 * q;
        hs[r0 * 260 + col]           = silu(a[0] + b1s[col]);
        hs[r0 * 260 + col + 1]       = silu(a[1] + b1s[col + 1]);
        hs[(r0 + 8) * 260 + col]     = silu(a[2] + b1s[col]);
        hs[(r0 + 8) * 260 + col + 1] = silu(a[3] + b1s[col + 1]);
    }
}

// GEMM1 epilogue raw (no bias/silu) -> hs[32][260]
__device__ __forceinline__ void epi1_raw(const float* acc, float* hs,
                                         int wm, int wn, int lane) {
    const int g = lane >> 2, q = lane & 3;
#pragma unroll
    for (int nt = 0; nt < 8; ++nt) {
        const float* a  = acc + nt * 4;
        const int r0  = wm * 16 + g;
        const int col = wn * 64 + nt * 8 + 2 * q;
        *(float2*)&hs[r0 * 260 + col]       = make_float2(a[0], a[1]);
        *(float2*)&hs[(r0 + 8) * 260 + col] = make_float2(a[2], a[3]);
    }
}

// GEMM2 epilogue: bias -> ys[32][132]   (WNT=4)
__device__ __forceinline__ void epi2(const float* acc, float* ys, const float* b2s,
                                     int wm, int wn, int lane) {
    const int g = lane >> 2, q = lane & 3;
#pragma unroll
    for (int nt = 0; nt < 4; ++nt) {
        const float* a  = acc + nt * 4;
        const int r0  = wm * 16 + g;
        const int col = wn * 32 + nt * 8 + 2 * q;
        *(float2*)&ys[r0 * 132 + col]       = make_float2(a[0] + b2s[col], a[1] + b2s[col + 1]);
        *(float2*)&ys[(r0 + 8) * 132 + col] = make_float2(a[2] + b2s[col], a[3] + b2s[col + 1]);
    }
}

// ---------------------------------------------------------------------------
// Kernel P: node projections P_s = sender_x@W1s, P_r = receiver_x@W1r (raw)
// ---------------------------------------------------------------------------
__global__ __launch_bounds__(NTHR) void proj_kernel(
    const float* __restrict__ xs_, const float* __restrict__ xr_, int nb) {
    extern __shared__ float sm[];
    float* A  = sm;            // [32][132]
    float* sB = sm + 4224;

    int b = blockIdx.x;
    const float* x; const float* Wp; float* P;
    if (b < nb) { x = xs_; Wp = g_wp + OFF_W1S; P = g_Ps; }
    else        { b -= nb; x = xr_; Wp = g_wp + OFF_W1R; P = g_Pr; }

    const int tid = threadIdx.x;
    const int warp = tid >> 5, lane = tid & 31;
    const int wm = warp >> 2, wn = warp & 3;
    const int i0 = b * TM;

    for (int i = tid; i < TM * 32; i += NTHR) {
        const int m = i / 32, c4 = (i % 32) * 4;
        *(float4*)&A[m * 132 + c4] = *(const float4*)&x[(size_t)(i0 + m) * D + c4];
    }

    float acc[32];
    warp_gemm<128, 256, 8>(A, 132, Wp, sB, acc, wm, wn, lane, tid);

    const int g = lane >> 2, q = lane & 3;
#pragma unroll
    for (int nt = 0; nt < 8; ++nt) {
        const float* a  = acc + nt * 4;
        const int r0  = wm * 16 + g;
        const int col = wn * 64 + nt * 8 + 2 * q;
        *(float2*)&P[(size_t)(i0 + r0) * HID + col]     = make_float2(a[0], a[1]);
        *(float2*)&P[(size_t)(i0 + r0 + 8) * HID + col] = make_float2(a[2], a[3]);
    }
}

// ---------------------------------------------------------------------------
// Kernel A: edge MLP via split GEMM1 (edge part only) + gathered P_s/P_r
// ---------------------------------------------------------------------------
__global__ __launch_bounds__(NTHR) void edge_kernel(
    const float* __restrict__ edge_attr, const void* __restrict__ edge_index,
    const float* __restrict__ eb1, const float* __restrict__ eb2,
    const float* __restrict__ eg, const float* __restrict__ ebeta,
    float* __restrict__ edge_out, int E, int N) {
    extern __shared__ float sm[];
    float* hs = sm;              // [32][260]
    float* A  = sm + A_OFF;      // [32][132] (also ys after GEMM2)
    float* ys = sm + A_OFF;
    float* sB = sm + SB_OFF;
    __shared__ int s_src[TM], s_dst[TM];
    __shared__ float s_b1[HID], s_b2[D], s_g[D], s_bt[D];

    const int tid = threadIdx.x;
    const int warp = tid >> 5, lane = tid & 31;
    const int wm = warp >> 2, wn = warp & 3;
    const int e0 = blockIdx.x * TM;

    if (tid < TM)          s_src[tid]      = load_index(edge_index, e0 + tid, N);
    else if (tid < 2 * TM) s_dst[tid - TM] = load_index(edge_index, (size_t)E + e0 + tid - TM, N);
    if (tid < HID) s_b1[tid] = eb1[tid];
    if (tid < D) { s_b2[tid] = eb2[tid]; s_g[tid] = eg[tid]; s_bt[tid] = ebeta[tid]; }

    // A = edge_attr tile (contiguous rows, no indexing)
    for (int i = tid; i < TM * 32; i += NTHR) {
        const int m = i / 32, c4 = (i % 32) * 4;
        *(float4*)&A[m * 132 + c4] = *(const float4*)&edge_attr[(size_t)(e0 + m) * D + c4];
    }

    float acc1[32];
    warp_gemm<128, 256, 8>(A, 132, g_wp + OFF_W1E, sB, acc1, wm, wn, lane, tid);
    epi1_raw(acc1, hs, wm, wn, lane);
    __syncthreads();

    // hs = silu(hs + P_s[src] + P_r[dst] + b1)   (coalesced L2-resident reads)
    for (int i = tid; i < TM * 64; i += NTHR) {
        const int m = i >> 6, c4 = (i & 63) * 4;
        float4 h = *(float4*)&hs[m * 260 + c4];
        const float4 ps = __ldg((const float4*)&g_Ps[(size_t)s_src[m] * HID + c4]);
        const float4 pr = __ldg((const float4*)&g_Pr[(size_t)s_dst[m] * HID + c4]);
        h.x = silu(h.x + ps.x + pr.x + s_b1[c4 + 0]);
        h.y = silu(h.y + ps.y + pr.y + s_b1[c4 + 1]);
        h.z = silu(h.z + ps.z + pr.z + s_b1[c4 + 2]);
        h.w = silu(h.w + ps.w + pr.w + s_b1[c4 + 3]);
        *(float4*)&hs[m * 260 + c4] = h;
    }
    // (warp_gemm's internal first __syncthreads orders these writes)

    float acc2[16];
    warp_gemm<256, 128, 4>(hs, 260, g_wp + OFF_EW2, sB, acc2, wm, wn, lane, tid);
    epi2(acc2, ys, s_b2, wm, wn, lane);
    __syncthreads();

    // LN + residual + scatter, 4 rows per warp
    for (int r = warp * 4; r < warp * 4 + 4; ++r) {
        float v[4], s = 0.f, ss = 0.f;
#pragma unroll
        for (int j = 0; j < 4; ++j) {
            v[j] = ys[r * 132 + lane + 32 * j];
            s += v[j]; ss += v[j] * v[j];
        }
#pragma unroll
        for (int o = 16; o > 0; o >>= 1) {
            s  += __shfl_xor_sync(0xFFFFFFFFu, s,  o);
            ss += __shfl_xor_sync(0xFFFFFFFFu, ss, o);
        }
        const float mu  = s * (1.f / D);
        const float inv = rsqrtf(ss * (1.f / D) - mu * mu + 1e-5f);
        const int dn = s_dst[r];
        const size_t eoff = (size_t)(e0 + r) * D;
#pragma unroll
        for (int j = 0; j < 4; ++j) {
            const int c = lane + 32 * j;
            const float p = (v[j] - mu) * inv * s_g[c] + s_bt[c];
            edge_out[eoff + c] = edge_attr[eoff + c] + p;
            atomicAdd(&g_agg[(size_t)dn * D + c], p);
        }
        if (lane == 0) atomicAdd(&g_cnt[dn], 1.f);
    }
}

// ---------------------------------------------------------------------------
// Kernel B: node MLP (2D->H->D) + LN + residual
// ---------------------------------------------------------------------------
__global__ __launch_bounds__(NTHR) void node_kernel(
    const float* __restrict__ receiver_x,
    const float* __restrict__ nb1, const float* __restrict__ nb2,
    const float* __restrict__ ng, const float* __restrict__ nbeta,
    float* __restrict__ receiver_out) {
    extern __shared__ float sm[];
    float* hs = sm;              // [32][260] — A for GEMM1 also lives here
    float* A  = sm;
    float* ys = sm + A_OFF;
    float* sB = sm + SB_OFF;
    __shared__ float s_inv[TM];
    __shared__ float s_b1[HID], s_b2[D], s_g[D], s_bt[D];

    const int tid = threadIdx.x;
    const int warp = tid >> 5, lane = tid & 31;
    const int wm = warp >> 2, wn = warp & 3;
    const int i0 = blockIdx.x * TM;

    if (tid < TM) s_inv[tid] = 1.f / fmaxf(g_cnt[i0 + tid], 1.f);
    if (tid < HID) s_b1[tid] = nb1[tid];
    if (tid < D) { s_b2[tid] = nb2[tid]; s_g[tid] = ng[tid]; s_bt[tid] = nbeta[tid]; }
    __syncthreads();

    for (int i = tid; i < TM * 64; i += NTHR) {
        const int m = i / 64, c4 = (i % 64) * 4;
        float4 v;
        if (c4 < 128) {
            v = *(const float4*)&receiver_x[(size_t)(i0 + m) * D + c4];
        } else {
            v = *(const float4*)&g_agg[(size_t)(i0 + m) * D + (c4 - 128)];
            const float sc = s_inv[m];
            v.x *= sc; v.y *= sc; v.z *= sc; v.w *= sc;
        }
        *(float4*)&A[m * 260 + c4] = v;
    }

    float acc1[32];
    warp_gemm<256, 256, 8>(A, 260, g_wp + OFF_NW1, sB, acc1, wm, wn, lane, tid);
    epi1(acc1, hs, s_b1, wm, wn, lane);
    __syncthreads();

    float acc2[16];
    warp_gemm<256, 128, 4>(hs, 260, g_wp + OFF_NW2, sB, acc2, wm, wn, lane, tid);
    epi2(acc2, ys, s_b2, wm, wn, lane);
    __syncthreads();

    for (int r = warp * 4; r < warp * 4 + 4; ++r) {
        float v[4], s = 0.f, ss = 0.f;
#pragma unroll
        for (int j = 0; j < 4; ++j) {
            v[j] = ys[r * 132 + lane + 32 * j];
            s += v[j]; ss += v[j] * v[j];
        }
#pragma unroll
        for (int o = 16; o > 0; o >>= 1) {
            s  += __shfl_xor_sync(0xFFFFFFFFu, s,  o);
            ss += __shfl_xor_sync(0xFFFFFFFFu, ss, o);
        }
        const float mu  = s * (1.f / D);
        const float inv = rsqrtf(ss * (1.f / D) - mu * mu + 1e-5f);
        const size_t off = (size_t)(i0 + r) * D;
#pragma unroll
        for (int j = 0; j < 4; ++j) {
            const int c = lane + 32 * j;
            const float p = (v[j] - mu) * inv * s_g[c] + s_bt[c];
            receiver_out[off + c] = receiver_x[off + c] + p;
        }
    }
}

// ---------------------------------------------------------------------------
// Kernel C: sender MLP (D->H->D) + LN + residual
// ---------------------------------------------------------------------------
__global__ __launch_bounds__(NTHR) void sender_kernel(
    const float* __restrict__ sender_x,
    const float* __restrict__ sb1, const float* __restrict__ sb2,
    const float* __restrict__ sg, const float* __restrict__ sbeta,
    float* __restrict__ sender_out) {
    extern __shared__ float sm[];
    float* hs = sm;              // [32][260]
    float* A  = sm + A_OFF;      // [32][132], ys later
    float* ys = sm + A_OFF;
    float* sB = sm + SB_OFF;
    __shared__ float s_b1[HID], s_b2[D], s_g[D], s_bt[D];

    const int tid = threadIdx.x;
    const int warp = tid >> 5, lane = tid & 31;
    const int wm = warp >> 2, wn = warp & 3;
    const int i0 = blockIdx.x * TM;

    if (tid < HID) s_b1[tid] = sb1[tid];
    if (tid < D) { s_b2[tid] = sb2[tid]; s_g[tid] = sg[tid]; s_bt[tid] = sbeta[tid]; }

    for (int i = tid; i < TM * 32; i += NTHR) {
        const int m = i / 32, c4 = (i % 32) * 4;
        *(float4*)&A[m * 132 + c4] =
            *(const float4*)&sender_x[(size_t)(i0 + m) * D + c4];
    }

    float acc1[32];
    warp_gemm<128, 256, 8>(A, 132, g_wp + OFF_SW1, sB, acc1, wm, wn, lane, tid);
    epi1(acc1, hs, s_b1, wm, wn, lane);
    __syncthreads();

    float acc2[16];
    warp_gemm<256, 128, 4>(hs, 260, g_wp + OFF_SW2, sB, acc2, wm, wn, lane, tid);
    epi2(acc2, ys, s_b2, wm, wn, lane);
    __syncthreads();

    for (int r = warp * 4; r < warp * 4 + 4; ++r) {
        float v[4], s = 0.f, ss = 0.f;
#pragma unroll
        for (int j = 0; j < 4; ++j) {
            v[j] = ys[r * 132 + lane + 32 * j];
            s += v[j]; ss += v[j] * v[j];
        }
#pragma unroll
        for (int o = 16; o > 0; o >>= 1) {
            s  += __shfl_xor_sync(0xFFFFFFFFu, s,  o);
            ss += __shfl_xor_sync(0xFFFFFFFFu, ss, o);
        }
        const float mu  = s * (1.f / D);
        const float inv = rsqrtf(ss * (1.f / D) - mu * mu + 1e-5f);
        const size_t off = (size_t)(i0 + r) * D;
#pragma unroll
        for (int j = 0; j < 4; ++j) {
            const int c = lane + 32 * j;
            const float p = (v[j] - mu) * inv * s_g[c] + s_bt[c];
            sender_out[off + c] = sender_x[off + c] + p;
        }
    }
}

// ---------------------------------------------------------------------------
__global__ void zero_agg_kernel(int nAgg) {
    const int i = blockIdx.x * blockDim.x + threadIdx.x;
    if (i < nAgg) g_agg[i] = 0.f;
}
__global__ void zero_cnt_kernel(int nCnt) {
    const int i = blockIdx.x * blockDim.x + threadIdx.x;
    if (i < nCnt) g_cnt[i] = 0.f;
}

extern "C" void kernel_launch(void* const* d_in, const int* in_sizes, int n_in,
                              void* d_out, int out_size) {
    const float* sender_x   = (const float*)d_in[0];
    const float* receiver_x = (const float*)d_in[1];
    const float* edge_attr  = (const float*)d_in[2];
    const void*  edge_index = d_in[3];
    const float* ew1 = (const float*)d_in[4];
    const float* eb1 = (const float*)d_in[5];
    const float* ew2 = (const float*)d_in[6];
    const float* eb2 = (const float*)d_in[7];
    const float* eg  = (const float*)d_in[8];
    const float* ebt = (const float*)d_in[9];
    const float* nw1 = (const float*)d_in[10];
    const float* nb1 = (const float*)d_in[11];
    const float* nw2 = (const float*)d_in[12];
    const float* nb2 = (const float*)d_in[13];
    const float* ng  = (const float*)d_in[14];
    const float* nbt = (const float*)d_in[15];
    const float* sw1 = (const float*)d_in[16];
    const float* sb1 = (const float*)d_in[17];
    const float* sw2 = (const float*)d_in[18];
    const float* sb2 = (const float*)d_in[19];
    const float* sg  = (const float*)d_in[20];
    const float* sbt = (const float*)d_in[21];

    const int N = in_sizes[0] / D;     // 40000
    const int E = in_sizes[2] / D;     // 640000

    float* out          = (float*)d_out;
    float* sender_out   = out;
    float* receiver_out = out + (size_t)N * D;
    float* edge_out     = out + (size_t)2 * N * D;

    cudaFuncSetAttribute(edge_kernel,   cudaFuncAttributeMaxDynamicSharedMemorySize, SMEM_BYTES);
    cudaFuncSetAttribute(node_kernel,   cudaFuncAttributeMaxDynamicSharedMemorySize, SMEM_BYTES);
    cudaFuncSetAttribute(sender_kernel, cudaFuncAttributeMaxDynamicSharedMemorySize, SMEM_BYTES);
    cudaFuncSetAttribute(proj_kernel,   cudaFuncAttributeMaxDynamicSharedMemorySize, PROJ_SMEM);

    const int nAgg = N * D;
    const int nb = N / TM;             // 1250

    // Launch order chosen so edge_kernel is launch #6 (ncu -s 5 -c 1 captures it).
    detect_idx_kernel<<<1, 32>>>((const unsigned int*)edge_index);            // 1
    pack_all_kernel<<<288, 256>>>(ew1, ew2, nw1, nw2, sw1, sw2);              // 2
    zero_agg_kernel<<<(nAgg + 511) / 512, 512>>>(nAgg);                       // 3
    zero_cnt_kernel<<<(N + 511) / 512, 512>>>(N);                             // 4
    proj_kernel<<<2 * nb, NTHR, PROJ_SMEM>>>(sender_x, receiver_x, nb);       // 5
    edge_kernel<<<E / TM, NTHR, SMEM_BYTES>>>(edge_attr, edge_index,          // 6
                                              eb1, eb2, eg, ebt, edge_out, E, N);
    node_kernel<<<N / TM, NTHR, SMEM_BYTES>>>(receiver_x, nb1, nb2, ng, nbt, receiver_out);
    sender_kernel<<<N / TM, NTHR, SMEM_BYTES>>>(sender_x, sb1, sb2, sg, sbt, sender_out);
}

// round 7
// speedup vs baseline: 3.8746x; 1.0934x over previous
#include <cuda_runtime.h>
#include <cstdint>

#define D     128
#define HID   256
#define TM    32
#define NTHR  256
#define MAXN  40000
#define MAXE  640000

// small-kernel smem layout (floats): [0..8320) hs, [8320..12544) A/ys, [12544..20736) B dbuf
#define A_OFF    8320       // 32*260
#define SB_OFF   12544
#define SMEM_BYTES ((12544 + 8192) * 4)
#define PROJ_SMEM  ((4224 + 8192) * 4)

// persistent edge kernels
#define W1SZ 32768                       // 128x256 packed floats
#define E1_SMEM ((W1SZ + 8448) * 4)      // + A tile 64x132
#define E2_SMEM ((W1SZ + 16640) * 4)     // + hs tile 64x260

// Scratch (device globals: no allocations allowed)
__device__ float g_agg[(size_t)MAXN * D];
__device__ float g_cnt[MAXN];
__device__ int   g_idx_is64;
__device__ float g_Ps[(size_t)MAXN * HID];   // sender_x @ W1[0:128]
__device__ float g_Pr[(size_t)MAXN * HID];   // receiver_x @ W1[128:256]
__device__ float g_hs[(size_t)MAXE * HID];   // raw edge GEMM1 output
__device__ float g_wp[294912];               // packed tf32 weights
#define OFF_W1S 0
#define OFF_W1R 32768
#define OFF_W1E 65536
#define OFF_EW2 98304
#define OFF_NW1 131072
#define OFF_NW2 196608
#define OFF_SW1 229376
#define OFF_SW2 262144

// ---------------------------------------------------------------------------
__device__ __forceinline__ uint32_t f2tf(float x) {
    uint32_t r; asm("cvt.rna.tf32.f32 %0, %1;" : "=r"(r) : "f"(x)); return r;
}
__device__ __forceinline__ float silu(float v) { return v / (1.f + __expf(-v)); }

__device__ __forceinline__ void mma8(float* c, const uint32_t* a,
                                     uint32_t b0, uint32_t b1) {
    asm volatile(
        "mma.sync.aligned.m16n8k8.row.col.f32.tf32.tf32.f32 "
        "{%0,%1,%2,%3},{%4,%5,%6,%7},{%8,%9},{%0,%1,%2,%3};"
        : "+f"(c[0]), "+f"(c[1]), "+f"(c[2]), "+f"(c[3])
        : "r"(a[0]), "r"(a[1]), "r"(a[2]), "r"(a[3]), "r"(b0), "r"(b1));
}

__device__ __forceinline__ void red_add_v4(float* p, float4 v) {
    asm volatile("red.global.add.v4.f32 [%0], {%1,%2,%3,%4};"
                 :: "l"(p), "f"(v.x), "f"(v.y), "f"(v.z), "f"(v.w) : "memory");
}

// ---------------------------------------------------------------------------
__global__ void detect_idx_kernel(const unsigned int* __restrict__ raw) {
    if (threadIdx.x == 0 && blockIdx.x == 0) {
        int is64 = 1;
        for (int i = 0; i < 32; ++i)
            if (raw[2 * i + 1] != 0u) { is64 = 0; break; }
        g_idx_is64 = is64;
    }
}
__device__ __forceinline__ int load_index(const void* idx, size_t pos, int n) {
    int v;
    if (g_idx_is64) v = (int)((const long long*)idx)[pos];
    else            v = ((const int*)idx)[pos];
    return v < 0 ? 0 : (v >= n ? n - 1 : v);
}

// ---------------------------------------------------------------------------
// Pack all weight matrices into tf32 fragment order (single launch).
// ---------------------------------------------------------------------------
__global__ void pack_all_kernel(const float* __restrict__ ew1, const float* __restrict__ ew2,
                                const float* __restrict__ nw1, const float* __restrict__ nw2,
                                const float* __restrict__ sw1, const float* __restrict__ sw2) {
    int b = blockIdx.x;
    const float* W; int off, K, Nn;
    if      (b < 32)  { W = ew1;             off = OFF_W1S; K = 128; Nn = 256; }
    else if (b < 64)  { W = ew1 + 128 * HID; off = OFF_W1R; K = 128; Nn = 256; b -= 32; }
    else if (b < 96)  { W = ew1 + 256 * HID; off = OFF_W1E; K = 128; Nn = 256; b -= 64; }
    else if (b < 128) { W = ew2;             off = OFF_EW2; K = 256; Nn = 128; b -= 96; }
    else if (b < 192) { W = nw1;             off = OFF_NW1; K = 256; Nn = 256; b -= 128; }
    else if (b < 224) { W = nw2;             off = OFF_NW2; K = 256; Nn = 128; b -= 192; }
    else if (b < 256) { W = sw1;             off = OFF_SW1; K = 128; Nn = 256; b -= 224; }
    else              { W = sw2;             off = OFF_SW2; K = 256; Nn = 128; b -= 256; }
    const int i = b * blockDim.x + threadIdx.x;
    const int total = (K / 8) * (Nn / 16) * 32;
    if (i >= total) return;
    const int lane = i & 31, rest = i >> 5;
    const int NP = Nn / 16;
    const int p = rest % NP, s = rest / NP;
    const int g = lane >> 2, q = lane & 3;
    const float* r0 = W + (size_t)(s * 8 + q) * Nn + p * 16 + g;
    const float* r1 = W + (size_t)(s * 8 + q + 4) * Nn + p * 16 + g;
    float4 v;
    v.x = __uint_as_float(f2tf(r0[0]));
    v.y = __uint_as_float(f2tf(r1[0]));
    v.z = __uint_as_float(f2tf(r0[8]));
    v.w = __uint_as_float(f2tf(r1[8]));
    ((float4*)(g_wp + off))[i] = v;
}

// ---------------------------------------------------------------------------
// Streaming warp GEMM (8 warps = 2Mx4N, warp tile M16xN(8*WNT)) — small kernels
// ---------------------------------------------------------------------------
template <int KIN, int NOUT, int WNT>
__device__ __forceinline__ void warp_gemm(const float* __restrict__ As, int astride,
                                          const float* __restrict__ Wp,
                                          float* __restrict__ sB,
                                          float* __restrict__ acc,
                                          int wm, int wn, int lane, int tid) {
    constexpr int NP    = NOUT / 16;
    constexpr int WNP   = WNT / 2;
    constexpr int SLICE = NP * 128;
    constexpr int STAGE = 2 * SLICE;
    constexpr int NST   = KIN / 16;
    constexpr int PF    = STAGE / (4 * NTHR);
    const int g = lane >> 2, q = lane & 3;

#pragma unroll
    for (int i = 0; i < WNT * 4; ++i) acc[i] = 0.f;

    {
        const float4* src = (const float4*)Wp;
        float4* dst = (float4*)sB;
#pragma unroll
        for (int i = 0; i < PF; ++i) dst[i * NTHR + tid] = src[i * NTHR + tid];
    }
    __syncthreads();

#pragma unroll 1
    for (int st = 0; st < NST; ++st) {
        float4 pf[PF];
        if (st + 1 < NST) {
            const float4* src = (const float4*)(Wp + (size_t)(st + 1) * STAGE);
#pragma unroll
            for (int i = 0; i < PF; ++i) pf[i] = src[i * NTHR + tid];
        }
        const float* bb = sB + (st & 1) * STAGE;
#pragma unroll
        for (int s2 = 0; s2 < 2; ++s2) {
            const int k0 = st * 16 + s2 * 8;
            uint32_t af[4];
            const float* ap = As + (wm * 16 + g) * astride + k0 + q;
            af[0] = f2tf(ap[0]);
            af[1] = f2tf(ap[8 * astride]);
            af[2] = f2tf(ap[4]);
            af[3] = f2tf(ap[8 * astride + 4]);
#pragma unroll
            for (int p = 0; p < WNP; ++p) {
                const float4 bv =
                    *(const float4*)(bb + ((s2 * NP + wn * WNP + p) * 32 + lane) * 4);
                mma8(acc + (2 * p) * 4,     af, __float_as_uint(bv.x), __float_as_uint(bv.y));
                mma8(acc + (2 * p + 1) * 4, af, __float_as_uint(bv.z), __float_as_uint(bv.w));
            }
        }
        if (st + 1 < NST) {
            float4* dst = (float4*)(sB + ((st + 1) & 1) * STAGE);
#pragma unroll
            for (int i = 0; i < PF; ++i) dst[i * NTHR + tid] = pf[i];
        }
        __syncthreads();
    }
}

// ---------------------------------------------------------------------------
// Resident-B warp GEMM (B fully in smem; NO barriers inside).
// Warp tile M16 x (8*WNT); works for 8- or 16-warp grids via wm/wn.
// ---------------------------------------------------------------------------
template <int KIN, int NOUT, int WNT>
__device__ __forceinline__ void gemm_res(const float* __restrict__ As, int astride,
                                         const float* __restrict__ sW,
                                         float* __restrict__ acc,
                                         int wm, int wn, int lane) {
    constexpr int NP  = NOUT / 16;
    constexpr int WNP = WNT / 2;
    const int g = lane >> 2, q = lane & 3;
#pragma unroll
    for (int i = 0; i < WNT * 4; ++i) acc[i] = 0.f;
#pragma unroll 4
    for (int s = 0; s < KIN / 8; ++s) {
        uint32_t af[4];
        const float* ap = As + (wm * 16 + g) * astride + s * 8 + q;
        af[0] = f2tf(ap[0]);
        af[1] = f2tf(ap[8 * astride]);
        af[2] = f2tf(ap[4]);
        af[3] = f2tf(ap[8 * astride + 4]);
#pragma unroll
        for (int p = 0; p < WNP; ++p) {
            const float4 bv = *(const float4*)(sW + ((s * NP + wn * WNP + p) * 32 + lane) * 4);
            mma8(acc + (2 * p) * 4,     af, __float_as_uint(bv.x), __float_as_uint(bv.y));
            mma8(acc + (2 * p + 1) * 4, af, __float_as_uint(bv.z), __float_as_uint(bv.w));
        }
    }
}

// GEMM1 epilogue: bias + SiLU -> hs[.][260]   (WNT=8)
__device__ __forceinline__ void epi1(const float* acc, float* hs, const float* b1s,
                                     int wm, int wn, int lane) {
    const int g = lane >> 2, q = lane & 3;
#pragma unroll
    for (int nt = 0; nt < 8; ++nt) {
        const float* a  = acc + nt * 4;
        const int r0  = wm * 16 + g;
        const int col = wn * 64 + nt * 8 + 2 * q;
        hs[r0 * 260 + col]           = silu(a[0] + b1s[col]);
        hs[r0 * 260 + col + 1]       = silu(a[1] + b1s[col + 1]);
        hs[(r0 + 8) * 260 + col]     = silu(a[2] + b1s[col]);
        hs[(r0 + 8) * 260 + col + 1] = silu(a[3] + b1s[col + 1]);
    }
}

// GEMM2 epilogue: bias -> ys[.][132]   (WNT=4)
__device__ __forceinline__ void epi2(const float* acc, float* ys, const float* b2s,
                                     int wm, int wn, int lane) {
    const int g = lane >> 2, q = lane & 3;
#pragma unroll
    for (int nt = 0; nt < 4; ++nt) {
        const float* a  = acc + nt * 4;
        const int r0  = wm * 16 + g;
        const int col = wn * 32 + nt * 8 + 2 * q;
        *(float2*)&ys[r0 * 132 + col]       = make_float2(a[0] + b2s[col], a[1] + b2s[col + 1]);
        *(float2*)&ys[(r0 + 8) * 132 + col] = make_float2(a[2] + b2s[col], a[3] + b2s[col + 1]);
    }
}

// ---------------------------------------------------------------------------
// Kernel P: node projections P_s = sender_x@W1s, P_r = receiver_x@W1r (raw)
// ---------------------------------------------------------------------------
__global__ __launch_bounds__(NTHR) void proj_kernel(
    const float* __restrict__ xs_, const float* __restrict__ xr_, int nb) {
    extern __shared__ float sm[];
    float* A  = sm;            // [32][132]
    float* sB = sm + 4224;

    int b = blockIdx.x;
    const float* x; const float* Wp; float* P;
    if (b < nb) { x = xs_; Wp = g_wp + OFF_W1S; P = g_Ps; }
    else        { b -= nb; x = xr_; Wp = g_wp + OFF_W1R; P = g_Pr; }

    const int tid = threadIdx.x;
    const int warp = tid >> 5, lane = tid & 31;
    const int wm = warp >> 2, wn = warp & 3;
    const int i0 = b * TM;

    for (int i = tid; i < TM * 32; i += NTHR) {
        const int m = i / 32, c4 = (i % 32) * 4;
        *(float4*)&A[m * 132 + c4] = *(const float4*)&x[(size_t)(i0 + m) * D + c4];
    }

    float acc[32];
    warp_gemm<128, 256, 8>(A, 132, Wp, sB, acc, wm, wn, lane, tid);

    const int g = lane >> 2, q = lane & 3;
#pragma unroll
    for (int nt = 0; nt < 8; ++nt) {
        const float* a  = acc + nt * 4;
        const int r0  = wm * 16 + g;
        const int col = wn * 64 + nt * 8 + 2 * q;
        *(float2*)&P[(size_t)(i0 + r0) * HID + col]     = make_float2(a[0], a[1]);
        *(float2*)&P[(size_t)(i0 + r0 + 8) * HID + col] = make_float2(a[2], a[3]);
    }
}

// ---------------------------------------------------------------------------
// Kernel E1 (persistent): raw edge GEMM1 — W1E resident in smem.
// 512 threads = 16 warps (4M x 4N), tile = 64 edges.
// ---------------------------------------------------------------------------
__global__ __launch_bounds__(512) void e1_kernel(const float* __restrict__ edge_attr,
                                                 int ntiles) {
    extern __shared__ float sm[];
    float* sW = sm;            // 32768 floats (packed W1E)
    float* A  = sm + W1SZ;     // [64][132]

    const int tid = threadIdx.x;
    const int warp = tid >> 5, lane = tid & 31;
    const int wm = warp >> 2, wn = warp & 3;

    {   // weights once
        const float4* src = (const float4*)(g_wp + OFF_W1E);
        float4* dst = (float4*)sW;
        for (int i = tid; i < W1SZ / 4; i += 512) dst[i] = src[i];
    }

    int t = blockIdx.x;
    float4 pf[4];
    if (t < ntiles) {
        const float4* src = (const float4*)(edge_attr + (size_t)t * 64 * D);
#pragma unroll
        for (int k = 0; k < 4; ++k) pf[k] = src[tid + k * 512];
    }
    __syncthreads();   // weights ready

#pragma unroll 1
    for (; t < ntiles; t += gridDim.x) {
#pragma unroll
        for (int k = 0; k < 4; ++k) {
            const int j = tid + k * 512;
            *(float4*)&A[(j >> 5) * 132 + (j & 31) * 4] = pf[k];
        }
        __syncthreads();   // A ready

        const int tn = t + gridDim.x;
        if (tn < ntiles) {
            const float4* src = (const float4*)(edge_attr + (size_t)tn * 64 * D);
#pragma unroll
            for (int k = 0; k < 4; ++k) pf[k] = src[tid + k * 512];
        }

        float acc[32];
        gemm_res<128, 256, 8>(A, 132, sW, acc, wm, wn, lane);

        const int g = lane >> 2, q = lane & 3;
        const size_t base = (size_t)t * 64;
#pragma unroll
        for (int nt = 0; nt < 8; ++nt) {
            const float* a  = acc + nt * 4;
            const int r0  = wm * 16 + g;
            const int col = wn * 64 + nt * 8 + 2 * q;
            *(float2*)&g_hs[(base + r0) * HID + col]     = make_float2(a[0], a[1]);
            *(float2*)&g_hs[(base + r0 + 8) * HID + col] = make_float2(a[2], a[3]);
        }
        __syncthreads();   // A consumed
    }
}

// ---------------------------------------------------------------------------
// Kernel E2 (persistent): silu(hs + Ps + Pr + b1) -> GEMM2 -> LN -> scatter.
// 512 threads = 16 warps; EW2 resident in smem; tile = 64 edges.
// ---------------------------------------------------------------------------
__global__ __launch_bounds__(512) void e2_kernel(
    const float* __restrict__ edge_attr, const void* __restrict__ edge_index,
    const float* __restrict__ eb1, const float* __restrict__ eb2,
    const float* __restrict__ eg, const float* __restrict__ ebeta,
    float* __restrict__ edge_out, int E, int N, int ntiles) {
    extern __shared__ float sm[];
    float* sW = sm;            // 32768 floats (packed EW2)
    float* hs = sm + W1SZ;     // [64][260]
    float* ys = sm + W1SZ;     // alias (8448 floats, used after GEMM2 reads done)
    __shared__ int s_src[64], s_dst[64];
    __shared__ float s_b1[HID], s_b2[D], s_g[D], s_bt[D];

    const int tid = threadIdx.x;
    const int warp = tid >> 5, lane = tid & 31;
    const int wm = warp >> 2, wn = warp & 3;

    {
        const float4* src = (const float4*)(g_wp + OFF_EW2);
        float4* dst = (float4*)sW;
        for (int i = tid; i < W1SZ / 4; i += 512) dst[i] = src[i];
    }
    if (tid < HID) s_b1[tid] = eb1[tid];
    if (tid < D) { s_b2[tid] = eb2[tid]; s_g[tid] = eg[tid]; s_bt[tid] = ebeta[tid]; }

#pragma unroll 1
    for (int t = blockIdx.x; t < ntiles; t += gridDim.x) {
        __syncthreads();   // prev tile fully done (also first-iter: weights/bias ready)
        if (tid < 64)        s_src[tid]      = load_index(edge_index, (size_t)t * 64 + tid, N);
        else if (tid < 128)  s_dst[tid - 64] = load_index(edge_index, (size_t)E + t * 64 + (tid - 64), N);
        __syncthreads();   // indices ready

        // hs = silu(raw + Ps[src] + Pr[dst] + b1)
        for (int i = tid; i < 64 * 64; i += 512) {
            const int m = i >> 6, c4 = (i & 63) * 4;
            float4 h = *(const float4*)&g_hs[((size_t)t * 64 + m) * HID + c4];
            const float4 ps = __ldg((const float4*)&g_Ps[(size_t)s_src[m] * HID + c4]);
            const float4 pr = __ldg((const float4*)&g_Pr[(size_t)s_dst[m] * HID + c4]);
            h.x = silu(h.x + ps.x + pr.x + s_b1[c4 + 0]);
            h.y = silu(h.y + ps.y + pr.y + s_b1[c4 + 1]);
            h.z = silu(h.z + ps.z + pr.z + s_b1[c4 + 2]);
            h.w = silu(h.w + ps.w + pr.w + s_b1[c4 + 3]);
            *(float4*)&hs[m * 260 + c4] = h;
        }
        __syncthreads();   // hs ready

        float acc[16];
        gemm_res<256, 128, 4>(hs, 260, sW, acc, wm, wn, lane);
        __syncthreads();   // all hs reads done (ys aliases hs)

        epi2(acc, ys, s_b2, wm, wn, lane);
        __syncthreads();   // ys ready

        // LN + residual + scatter: 4 rows/warp, float4 per lane
#pragma unroll
        for (int r = warp * 4; r < warp * 4 + 4; ++r) {
            const float4 v = *(const float4*)&ys[r * 132 + lane * 4];
            float s  = v.x + v.y + v.z + v.w;
            float ss = v.x * v.x + v.y * v.y + v.z * v.z + v.w * v.w;
#pragma unroll
            for (int o = 16; o > 0; o >>= 1) {
                s  += __shfl_xor_sync(0xFFFFFFFFu, s,  o);
                ss += __shfl_xor_sync(0xFFFFFFFFu, ss, o);
            }
            const float mu  = s * (1.f / D);
            const float inv = rsqrtf(ss * (1.f / D) - mu * mu + 1e-5f);
            const int dn = s_dst[r];
            const size_t eoff = ((size_t)t * 64 + r) * D;
            const int c = lane * 4;
            float4 p;
            p.x = (v.x - mu) * inv * s_g[c + 0] + s_bt[c + 0];
            p.y = (v.y - mu) * inv * s_g[c + 1] + s_bt[c + 1];
            p.z = (v.z - mu) * inv * s_g[c + 2] + s_bt[c + 2];
            p.w = (v.w - mu) * inv * s_g[c + 3] + s_bt[c + 3];
            const float4 att = *(const float4*)&edge_attr[eoff + c];
            float4 o4;
            o4.x = att.x + p.x; o4.y = att.y + p.y; o4.z = att.z + p.z; o4.w = att.w + p.w;
            *(float4*)&edge_out[eoff + c] = o4;
            red_add_v4(&g_agg[(size_t)dn * D + c], p);
            if (lane == 0) atomicAdd(&g_cnt[dn], 1.f);
        }
    }
}

// ---------------------------------------------------------------------------
// Kernel B: node MLP (2D->H->D) + LN + residual
// ---------------------------------------------------------------------------
__global__ __launch_bounds__(NTHR) void node_kernel(
    const float* __restrict__ receiver_x,
    const float* __restrict__ nb1, const float* __restrict__ nb2,
    const float* __restrict__ ng, const float* __restrict__ nbeta,
    float* __restrict__ receiver_out) {
    extern __shared__ float sm[];
    float* hs = sm;              // [32][260]
    float* A  = sm;
    float* ys = sm + A_OFF;
    float* sB = sm + SB_OFF;
    __shared__ float s_inv[TM];
    __shared__ float s_b1[HID], s_b2[D], s_g[D], s_bt[D];

    const int tid = threadIdx.x;
    const int warp = tid >> 5, lane = tid & 31;
    const int wm = warp >> 2, wn = warp & 3;
    const int i0 = blockIdx.x * TM;

    if (tid < TM) s_inv[tid] = 1.f / fmaxf(g_cnt[i0 + tid], 1.f);
    if (tid < HID) s_b1[tid] = nb1[tid];
    if (tid < D) { s_b2[tid] = nb2[tid]; s_g[tid] = ng[tid]; s_bt[tid] = nbeta[tid]; }
    __syncthreads();

    for (int i = tid; i < TM * 64; i += NTHR) {
        const int m = i / 64, c4 = (i % 64) * 4;
        float4 v;
        if (c4 < 128) {
            v = *(const float4*)&receiver_x[(size_t)(i0 + m) * D + c4];
        } else {
            v = *(const float4*)&g_agg[(size_t)(i0 + m) * D + (c4 - 128)];
            const float sc = s_inv[m];
            v.x *= sc; v.y *= sc; v.z *= sc; v.w *= sc;
        }
        *(float4*)&A[m * 260 + c4] = v;
    }

    float acc1[32];
    warp_gemm<256, 256, 8>(A, 260, g_wp + OFF_NW1, sB, acc1, wm, wn, lane, tid);
    epi1(acc1, hs, s_b1, wm, wn, lane);
    __syncthreads();

    float acc2[16];
    warp_gemm<256, 128, 4>(hs, 260, g_wp + OFF_NW2, sB, acc2, wm, wn, lane, tid);
    epi2(acc2, ys, s_b2, wm, wn, lane);
    __syncthreads();

    for (int r = warp * 4; r < warp * 4 + 4; ++r) {
        float v[4], s = 0.f, ss = 0.f;
#pragma unroll
        for (int j = 0; j < 4; ++j) {
            v[j] = ys[r * 132 + lane + 32 * j];
            s += v[j]; ss += v[j] * v[j];
        }
#pragma unroll
        for (int o = 16; o > 0; o >>= 1) {
            s  += __shfl_xor_sync(0xFFFFFFFFu, s,  o);
            ss += __shfl_xor_sync(0xFFFFFFFFu, ss, o);
        }
        const float mu  = s * (1.f / D);
        const float inv = rsqrtf(ss * (1.f / D) - mu * mu + 1e-5f);
        const size_t off = (size_t)(i0 + r) * D;
#pragma unroll
        for (int j = 0; j < 4; ++j) {
            const int c = lane + 32 * j;
            const float p = (v[j] - mu) * inv * s_g[c] + s_bt[c];
            receiver_out[off + c] = receiver_x[off + c] + p;
        }
    }
}

// ---------------------------------------------------------------------------
// Kernel C: sender MLP (D->H->D) + LN + residual
// ---------------------------------------------------------------------------
__global__ __launch_bounds__(NTHR) void sender_kernel(
    const float* __restrict__ sender_x,
    const float* __restrict__ sb1, const float* __restrict__ sb2,
    const float* __restrict__ sg, const float* __restrict__ sbeta,
    float* __restrict__ sender_out) {
    extern __shared__ float sm[];
    float* hs = sm;              // [32][260]
    float* A  = sm + A_OFF;      // [32][132], ys later
    float* ys = sm + A_OFF;
    float* sB = sm + SB_OFF;
    __shared__ float s_b1[HID], s_b2[D], s_g[D], s_bt[D];

    const int tid = threadIdx.x;
    const int warp = tid >> 5, lane = tid & 31;
    const int wm = warp >> 2, wn = warp & 3;
    const int i0 = blockIdx.x * TM;

    if (tid < HID) s_b1[tid] = sb1[tid];
    if (tid < D) { s_b2[tid] = sb2[tid]; s_g[tid] = sg[tid]; s_bt[tid] = sbeta[tid]; }

    for (int i = tid; i < TM * 32; i += NTHR) {
        const int m = i / 32, c4 = (i % 32) * 4;
        *(float4*)&A[m * 132 + c4] =
            *(const float4*)&sender_x[(size_t)(i0 + m) * D + c4];
    }

    float acc1[32];
    warp_gemm<128, 256, 8>(A, 132, g_wp + OFF_SW1, sB, acc1, wm, wn, lane, tid);
    epi1(acc1, hs, s_b1, wm, wn, lane);
    __syncthreads();

    float acc2[16];
    warp_gemm<256, 128, 4>(hs, 260, g_wp + OFF_SW2, sB, acc2, wm, wn, lane, tid);
    epi2(acc2, ys, s_b2, wm, wn, lane);
    __syncthreads();

    for (int r = warp * 4; r < warp * 4 + 4; ++r) {
        float v[4], s = 0.f, ss = 0.f;
#pragma unroll
        for (int j = 0; j < 4; ++j) {
            v[j] = ys[r * 132 + lane + 32 * j];
            s += v[j]; ss += v[j] * v[j];
        }
#pragma unroll
        for (int o = 16; o > 0; o >>= 1) {
            s  += __shfl_xor_sync(0xFFFFFFFFu, s,  o);
            ss += __shfl_xor_sync(0xFFFFFFFFu, ss, o);
        }
        const float mu  = s * (1.f / D);
        const float inv = rsqrtf(ss * (1.f / D) - mu * mu + 1e-5f);
        const size_t off = (size_t)(i0 + r) * D;
#pragma unroll
        for (int j = 0; j < 4; ++j) {
            const int c = lane + 32 * j;
            const float p = (v[j] - mu) * inv * s_g[c] + s_bt[c];
            sender_out[off + c] = sender_x[off + c] + p;
        }
    }
}

// ---------------------------------------------------------------------------
__global__ void zero_agg_kernel(int nAgg) {
    const int i = blockIdx.x * blockDim.x + threadIdx.x;
    if (i < nAgg) g_agg[i] = 0.f;
}
__global__ void zero_cnt_kernel(int nCnt) {
    const int i = blockIdx.x * blockDim.x + threadIdx.x;
    if (i < nCnt) g_cnt[i] = 0.f;
}

extern "C" void kernel_launch(void* const* d_in, const int* in_sizes, int n_in,
                              void* d_out, int out_size) {
    const float* sender_x   = (const float*)d_in[0];
    const float* receiver_x = (const float*)d_in[1];
    const float* edge_attr  = (const float*)d_in[2];
    const void*  edge_index = d_in[3];
    const float* ew1 = (const float*)d_in[4];
    const float* eb1 = (const float*)d_in[5];
    const float* ew2 = (const float*)d_in[6];
    const float* eb2 = (const float*)d_in[7];
    const float* eg  = (const float*)d_in[8];
    const float* ebt = (const float*)d_in[9];
    const float* nw1 = (const float*)d_in[10];
    const float* nb1 = (const float*)d_in[11];
    const float* nw2 = (const float*)d_in[12];
    const float* nb2 = (const float*)d_in[13];
    const float* ng  = (const float*)d_in[14];
    const float* nbt = (const float*)d_in[15];
    const float* sw1 = (const float*)d_in[16];
    const float* sb1 = (const float*)d_in[17];
    const float* sw2 = (const float*)d_in[18];
    const float* sb2 = (const float*)d_in[19];
    const float* sg  = (const float*)d_in[20];
    const float* sbt = (const float*)d_in[21];

    const int N = in_sizes[0] / D;     // 40000
    const int E = in_sizes[2] / D;     // 640000

    float* out          = (float*)d_out;
    float* sender_out   = out;
    float* receiver_out = out + (size_t)N * D;
    float* edge_out     = out + (size_t)2 * N * D;

    cudaFuncSetAttribute(e1_kernel,     cudaFuncAttributeMaxDynamicSharedMemorySize, E1_SMEM);
    cudaFuncSetAttribute(e2_kernel,     cudaFuncAttributeMaxDynamicSharedMemorySize, E2_SMEM);
    cudaFuncSetAttribute(node_kernel,   cudaFuncAttributeMaxDynamicSharedMemorySize, SMEM_BYTES);
    cudaFuncSetAttribute(sender_kernel, cudaFuncAttributeMaxDynamicSharedMemorySize, SMEM_BYTES);
    cudaFuncSetAttribute(proj_kernel,   cudaFuncAttributeMaxDynamicSharedMemorySize, PROJ_SMEM);

    const int nAgg = N * D;
    const int nb = N / TM;             // 1250
    const int ntiles = E / 64;         // 10000

    // Launch order: e1_kernel is launch #6 (ncu -s 5 -c 1 captures it).
    detect_idx_kernel<<<1, 32>>>((const unsigned int*)edge_index);            // 1
    pack_all_kernel<<<288, 256>>>(ew1, ew2, nw1, nw2, sw1, sw2);              // 2
    zero_agg_kernel<<<(nAgg + 511) / 512, 512>>>(nAgg);                       // 3
    zero_cnt_kernel<<<(N + 511) / 512, 512>>>(N);                             // 4
    proj_kernel<<<2 * nb, NTHR, PROJ_SMEM>>>(sender_x, receiver_x, nb);       // 5
    e1_kernel<<<148, 512, E1_SMEM>>>(edge_attr, ntiles);                      // 6
    e2_kernel<<<148, 512, E2_SMEM>>>(edge_attr, edge_index,                   // 7
                                     eb1, eb2, eg, ebt, edge_out, E, N, ntiles);
    node_kernel<<<N / TM, NTHR, SMEM_BYTES>>>(receiver_x, nb1, nb2, ng, nbt, receiver_out);
    sender_kernel<<<N / TM, NTHR, SMEM_BYTES>>>(sender_x, sb1, sb2, sg, sbt, sender_out);
}